// round 2
// baseline (speedup 1.0000x reference)
#include <cuda_runtime.h>
#include <math.h>

#define B_ 2
#define S_ 2048
#define D_ 1024
#define H_ 16
#define HD_ 64
#define LOG2E 1.4426950408889634f

// Scratch (static device globals: allocation-free, allowed by harness rules)
__device__ float g_q[B_*S_*D_];
__device__ float g_k[B_*S_*D_];
__device__ float g_v[B_*S_*D_];
__device__ float g_o[B_*S_*D_];

// ---------------------------------------------------------------------------
// C[M,N] = A[M,K] @ W[K,N] + bias  (all fp32 row-major)
// BM=BN=128, BK=8, 256 threads, 8x8 accum per thread, split 4+64 frag offsets
// ---------------------------------------------------------------------------
__global__ __launch_bounds__(256) void sgemm_bias(
    const float* __restrict__ A, const float* __restrict__ W,
    const float* __restrict__ bias, float* __restrict__ C,
    int M, int N, int K)
{
    __shared__ float As[8][128];   // A transposed: As[k][m]
    __shared__ float Bs[8][128];   // Bs[k][n]
    int tid = threadIdx.x;
    int tx = tid & 15, ty = tid >> 4;
    int bm = blockIdx.y * 128, bn = blockIdx.x * 128;
    int arow = tid >> 1, acol = (tid & 1) * 4;
    int brow = tid >> 5, bcol = (tid & 31) * 4;

    float acc[8][8];
    #pragma unroll
    for (int i = 0; i < 8; i++)
        #pragma unroll
        for (int j = 0; j < 8; j++) acc[i][j] = 0.f;

    const float* Aptr = A + (size_t)(bm + arow) * K + acol;
    const float* Wptr = W + (size_t)brow * N + bn + bcol;

    for (int k0 = 0; k0 < K; k0 += 8) {
        float4 av = *(const float4*)(Aptr + k0);
        As[acol + 0][arow] = av.x;
        As[acol + 1][arow] = av.y;
        As[acol + 2][arow] = av.z;
        As[acol + 3][arow] = av.w;
        *(float4*)&Bs[brow][bcol] = *(const float4*)(Wptr + (size_t)k0 * N);
        __syncthreads();
        #pragma unroll
        for (int k = 0; k < 8; k++) {
            float a[8], b[8];
            *(float4*)&a[0] = *(float4*)&As[k][ty * 4];
            *(float4*)&a[4] = *(float4*)&As[k][ty * 4 + 64];
            *(float4*)&b[0] = *(float4*)&Bs[k][tx * 4];
            *(float4*)&b[4] = *(float4*)&Bs[k][tx * 4 + 64];
            #pragma unroll
            for (int i = 0; i < 8; i++)
                #pragma unroll
                for (int j = 0; j < 8; j++)
                    acc[i][j] = fmaf(a[i], b[j], acc[i][j]);
        }
        __syncthreads();
    }

    #pragma unroll
    for (int i = 0; i < 8; i++) {
        int row = bm + ty * 4 + (i & 3) + (i >> 2) * 64;
        #pragma unroll
        for (int jb = 0; jb < 2; jb++) {
            int col = bn + tx * 4 + jb * 64;
            float4 bv = *(const float4*)&bias[col];
            float4 r;
            r.x = acc[i][jb * 4 + 0] + bv.x;
            r.y = acc[i][jb * 4 + 1] + bv.y;
            r.z = acc[i][jb * 4 + 2] + bv.z;
            r.w = acc[i][jb * 4 + 3] + bv.w;
            *(float4*)&C[(size_t)row * N + col] = r;
        }
    }
}

// ---------------------------------------------------------------------------
// RoPE in-place on q and k.  t = ((b*S + s)*H + h)*32 + i  (pair index)
// ---------------------------------------------------------------------------
__global__ void rope_kernel(float* __restrict__ q, float* __restrict__ k,
                            const float* __restrict__ freqs)
{
    int idx = blockIdx.x * blockDim.x + threadIdx.x;
    const int total = B_ * S_ * H_ * (HD_ / 2);  // 2^21
    float* p = q;
    int t = idx;
    if (t >= total) { p = k; t -= total; }
    int i = t & 31;
    int h = (t >> 5) & 15;
    int s = (t >> 9) & 2047;
    int b = t >> 20;
    float2 cs = *(const float2*)&freqs[s * 64 + i * 2];
    float2* addr = (float2*)&p[(b * S_ + s) * D_ + h * HD_ + 2 * i];
    float2 xv = *addr;
    float2 o;
    o.x = xv.x * cs.x - xv.y * cs.y;
    o.y = xv.x * cs.y + xv.y * cs.x;
    *addr = o;
}

// ---------------------------------------------------------------------------
// Flash attention, fp32. Per block: 64 queries of one (b,h). 64-key tiles.
// Qt/Kt stored transposed [hd][row] for vectorized frag loads; Ps aliases Kt.
// Thread grid 16x16; each thread owns a 4x4 patch (rows ty*4+i, cols tx*4+j).
// ---------------------------------------------------------------------------
#define ATTN_SMEM (3 * 64 * 68 * 4)

__global__ __launch_bounds__(256) void attn_kernel(
    const float* __restrict__ Q, const float* __restrict__ K,
    const float* __restrict__ V, float* __restrict__ O)
{
    extern __shared__ float sm[];
    float (*Qt)[68] = (float(*)[68])sm;                 // [hd][qrow]
    float (*Kt)[68] = (float(*)[68])(sm + 64 * 68);     // [hd][kcol]
    float (*Ps)[68] = (float(*)[68])(sm + 64 * 68);     // alias: [qrow][kcol]
    float (*Vs)[68] = (float(*)[68])(sm + 2 * 64 * 68); // [key][hd]

    int tid = threadIdx.x;
    int tx = tid & 15, ty = tid >> 4;
    int q0 = blockIdx.x * 64;
    int h = blockIdx.y, b = blockIdx.z;
    int lrow = tid >> 4;        // 0..15
    int lcol = (tid & 15) * 4;  // 0..60

    const float scale = 0.125f;  // 1/sqrt(64)

    // Load Q tile, transposed + pre-scaled
    #pragma unroll
    for (int rr = 0; rr < 4; rr++) {
        int r = lrow + rr * 16;
        float4 v4 = *(const float4*)&Q[(b * S_ + q0 + r) * D_ + h * HD_ + lcol];
        Qt[lcol + 0][r] = v4.x * scale;
        Qt[lcol + 1][r] = v4.y * scale;
        Qt[lcol + 2][r] = v4.z * scale;
        Qt[lcol + 3][r] = v4.w * scale;
    }

    float m_[4], l_[4], o_[4][4];
    #pragma unroll
    for (int i = 0; i < 4; i++) {
        m_[i] = -3.0e38f; l_[i] = 0.f;
        #pragma unroll
        for (int j = 0; j < 4; j++) o_[i][j] = 0.f;
    }

    for (int t = 0; t < S_ / 64; t++) {
        __syncthreads();  // prior-iter PV reads of Ps/Vs complete (covers Q store @ t=0)
        int k0 = t * 64;
        #pragma unroll
        for (int rr = 0; rr < 4; rr++) {
            int r = lrow + rr * 16;
            float4 kv = *(const float4*)&K[(b * S_ + k0 + r) * D_ + h * HD_ + lcol];
            Kt[lcol + 0][r] = kv.x;
            Kt[lcol + 1][r] = kv.y;
            Kt[lcol + 2][r] = kv.z;
            Kt[lcol + 3][r] = kv.w;
            float4 vv = *(const float4*)&V[(b * S_ + k0 + r) * D_ + h * HD_ + lcol];
            *(float4*)&Vs[r][lcol] = vv;
        }
        __syncthreads();

        // S = (Q*scale) @ K^T   (64x64x64)
        float s4[4][4];
        #pragma unroll
        for (int i = 0; i < 4; i++)
            #pragma unroll
            for (int j = 0; j < 4; j++) s4[i][j] = 0.f;

        #pragma unroll 8
        for (int kk = 0; kk < 64; kk++) {
            float4 qv = *(float4*)&Qt[kk][ty * 4];
            float4 kv = *(float4*)&Kt[kk][tx * 4];
            float qa[4] = {qv.x, qv.y, qv.z, qv.w};
            float kb[4] = {kv.x, kv.y, kv.z, kv.w};
            #pragma unroll
            for (int i = 0; i < 4; i++)
                #pragma unroll
                for (int j = 0; j < 4; j++)
                    s4[i][j] = fmaf(qa[i], kb[j], s4[i][j]);
        }

        __syncthreads();  // all Kt reads done before Ps overwrite

        // Online softmax (row stats across the 16 tx threads: width-16 shuffles)
        #pragma unroll
        for (int i = 0; i < 4; i++) {
            float mx = s4[i][0];
            mx = fmaxf(mx, s4[i][1]);
            mx = fmaxf(mx, s4[i][2]);
            mx = fmaxf(mx, s4[i][3]);
            #pragma unroll
            for (int off = 1; off < 16; off <<= 1)
                mx = fmaxf(mx, __shfl_xor_sync(0xffffffffu, mx, off, 16));
            float mnew = fmaxf(m_[i], mx);
            float alpha = exp2f((m_[i] - mnew) * LOG2E);
            m_[i] = mnew;
            float rs = 0.f;
            #pragma unroll
            for (int j = 0; j < 4; j++) {
                float p = exp2f((s4[i][j] - mnew) * LOG2E);
                s4[i][j] = p;
                rs += p;
            }
            #pragma unroll
            for (int off = 1; off < 16; off <<= 1)
                rs += __shfl_xor_sync(0xffffffffu, rs, off, 16);
            l_[i] = l_[i] * alpha + rs;
            #pragma unroll
            for (int j = 0; j < 4; j++) o_[i][j] *= alpha;
            *(float4*)&Ps[ty * 4 + i][tx * 4] =
                make_float4(s4[i][0], s4[i][1], s4[i][2], s4[i][3]);
        }
        __syncthreads();  // P visible to all

        // O += P @ V   (64x64x64)
        #pragma unroll 8
        for (int kk = 0; kk < 64; kk++) {
            float4 vv = *(float4*)&Vs[kk][tx * 4];
            float vb[4] = {vv.x, vv.y, vv.z, vv.w};
            float pa[4];
            #pragma unroll
            for (int i = 0; i < 4; i++) pa[i] = Ps[ty * 4 + i][kk];
            #pragma unroll
            for (int i = 0; i < 4; i++)
                #pragma unroll
                for (int j = 0; j < 4; j++)
                    o_[i][j] = fmaf(pa[i], vb[j], o_[i][j]);
        }
    }

    #pragma unroll
    for (int i = 0; i < 4; i++) {
        float inv = 1.f / l_[i];
        float4 r = make_float4(o_[i][0] * inv, o_[i][1] * inv,
                               o_[i][2] * inv, o_[i][3] * inv);
        *(float4*)&O[(b * S_ + q0 + ty * 4 + i) * D_ + h * HD_ + tx * 4] = r;
    }
}

// ---------------------------------------------------------------------------
// Launch: QKV GEMMs -> RoPE(q,k) -> flash attention -> output GEMM
// Inputs: x, freqs_cis, wq, bq, wk, bk, wv, bv, wo, bo, start_pos
// ---------------------------------------------------------------------------
extern "C" void kernel_launch(void* const* d_in, const int* in_sizes, int n_in,
                              void* d_out, int out_size)
{
    const float* x  = (const float*)d_in[0];
    const float* fr = (const float*)d_in[1];
    const float* wq = (const float*)d_in[2];
    const float* bq = (const float*)d_in[3];
    const float* wk = (const float*)d_in[4];
    const float* bk = (const float*)d_in[5];
    const float* wv = (const float*)d_in[6];
    const float* bv = (const float*)d_in[7];
    const float* wo = (const float*)d_in[8];
    const float* bo = (const float*)d_in[9];
    float* out = (float*)d_out;

    float *q, *k, *v, *o;
    cudaGetSymbolAddress((void**)&q, g_q);
    cudaGetSymbolAddress((void**)&k, g_k);
    cudaGetSymbolAddress((void**)&v, g_v);
    cudaGetSymbolAddress((void**)&o, g_o);

    cudaFuncSetAttribute(attn_kernel,
                         cudaFuncAttributeMaxDynamicSharedMemorySize, ATTN_SMEM);

    dim3 gg(D_ / 128, (B_ * S_) / 128);  // (8, 32)
    sgemm_bias<<<gg, 256>>>(x, wq, bq, q, B_ * S_, D_, D_);
    sgemm_bias<<<gg, 256>>>(x, wk, bk, k, B_ * S_, D_, D_);
    sgemm_bias<<<gg, 256>>>(x, wv, bv, v, B_ * S_, D_, D_);

    int pair_threads = 2 * B_ * S_ * H_ * (HD_ / 2);
    rope_kernel<<<pair_threads / 256, 256>>>(q, k, fr);

    attn_kernel<<<dim3(S_ / 64, H_, B_), 256, ATTN_SMEM>>>(q, k, v, o);

    sgemm_bias<<<gg, 256>>>(o, wo, bo, out, B_ * S_, D_, D_);
}

// round 3
// speedup vs baseline: 4.8403x; 4.8403x over previous
#include <cuda_runtime.h>
#include <cuda_fp16.h>
#include <math.h>
#include <stdint.h>

#define B_ 2
#define S_ 2048
#define D_ 1024
#define H_ 16
#define HD_ 64
#define LOG2E 1.4426950408889634f

// fp16 scratch (static device globals: allocation-free)
__device__ __half g_qh[B_*S_*D_];
__device__ __half g_kh[B_*S_*D_];
__device__ __half g_vh[B_*S_*D_];
__device__ __half g_oh[B_*S_*D_];

// ---------------------------------------------------------------------------
// helpers
// ---------------------------------------------------------------------------
__device__ __forceinline__ uint32_t s2u(const void* p) {
    return (uint32_t)__cvta_generic_to_shared(p);
}
__device__ __forceinline__ void ldsm4(uint32_t r[4], uint32_t a) {
    asm volatile("ldmatrix.sync.aligned.m8n8.x4.shared.b16 {%0,%1,%2,%3},[%4];\n"
        : "=r"(r[0]), "=r"(r[1]), "=r"(r[2]), "=r"(r[3]) : "r"(a));
}
__device__ __forceinline__ void ldsm4t(uint32_t r[4], uint32_t a) {
    asm volatile("ldmatrix.sync.aligned.m8n8.x4.trans.shared.b16 {%0,%1,%2,%3},[%4];\n"
        : "=r"(r[0]), "=r"(r[1]), "=r"(r[2]), "=r"(r[3]) : "r"(a));
}
__device__ __forceinline__ void mma_f16(float c[4], const uint32_t a[4], const uint32_t b[2]) {
    asm volatile(
        "mma.sync.aligned.m16n8k16.row.col.f32.f16.f16.f32 "
        "{%0,%1,%2,%3},{%4,%5,%6,%7},{%8,%9},{%0,%1,%2,%3};\n"
        : "+f"(c[0]), "+f"(c[1]), "+f"(c[2]), "+f"(c[3])
        : "r"(a[0]), "r"(a[1]), "r"(a[2]), "r"(a[3]), "r"(b[0]), "r"(b[1]));
}
__device__ __forceinline__ uint32_t pack_h2(float a, float b) {
    __half2 h = __floats2half2_rn(a, b);
    return *reinterpret_cast<uint32_t*>(&h);
}
// exp2 on the FMA pipe (avoids MUFU wall). x <= 0 expected; |rel err| ~2.4e-6.
__device__ __forceinline__ float fexp2(float x) {
    x = fmaxf(x, -120.f);
    float r = rintf(x);
    float f = x - r;                  // [-0.5, 0.5]
    float p = 1.3333558e-3f;
    p = fmaf(p, f, 9.6181291e-3f);
    p = fmaf(p, f, 5.5504109e-2f);
    p = fmaf(p, f, 2.4022651e-1f);
    p = fmaf(p, f, 6.9314718e-1f);
    p = fmaf(p, f, 1.0f);
    return __int_as_float(__float_as_int(p) + (((int)r) << 23));
}

// ---------------------------------------------------------------------------
// GEMM: C[M,N] = A[M,K] @ W[K,N] + bias.  A: float or half; W fp32; C: float or half.
// Block 128x128, BK=32, 8 warps (2m x 4n), warp tile 64x32, fp16 HMMA fp32-accum.
// ---------------------------------------------------------------------------
#define BK 32
#define AS_STRIDE 40    // 32 + 8 pad (80B rows: ldmatrix conflict-free, 16B aligned)
#define BS_STRIDE 136   // 128 + 8 pad (272B rows)

template<typename AT, typename OT>
__global__ __launch_bounds__(256) void gemm_mma(
    const AT* __restrict__ A, const float* __restrict__ W,
    const float* __restrict__ bias, OT* __restrict__ C,
    int M, int N, int K)
{
    __shared__ __align__(16) __half As[2][128 * AS_STRIDE];
    __shared__ __align__(16) __half Bs[2][BK * BS_STRIDE];

    int tid = threadIdx.x, lane = tid & 31, wid = tid >> 5;
    int wm = wid & 1, wn = wid >> 1;
    int bm = blockIdx.y * 128, bn = blockIdx.x * 128;

    float acc[4][4][4];
    #pragma unroll
    for (int i = 0; i < 4; i++)
        #pragma unroll
        for (int j = 0; j < 4; j++)
            #pragma unroll
            for (int c = 0; c < 4; c++) acc[i][j][c] = 0.f;

    int a_row = wm * 64 + (lane & 15);
    int a_colh = (lane >> 4) << 3;
    int b_krow = lane & 15;
    int b_coln = (lane >> 4) << 3;

    auto load_stage = [&](int s, int buf) {
        int k0 = s * BK;
        if constexpr (sizeof(AT) == 4) {
            #pragma unroll
            for (int p = 0; p < 4; p++) {
                int m = (tid >> 3) + p * 32, kq = (tid & 7) * 4;
                float4 v = *(const float4*)((const float*)A + (size_t)(bm + m) * K + k0 + kq);
                *(__half2*)&As[buf][m * AS_STRIDE + kq]     = __floats2half2_rn(v.x, v.y);
                *(__half2*)&As[buf][m * AS_STRIDE + kq + 2] = __floats2half2_rn(v.z, v.w);
            }
        } else {
            int m = tid >> 1, j = tid & 1;
            const uint4* src = (const uint4*)((const __half*)A + (size_t)(bm + m) * K + k0 + j * 16);
            *(uint4*)&As[buf][m * AS_STRIDE + j * 16]     = src[0];
            *(uint4*)&As[buf][m * AS_STRIDE + j * 16 + 8] = src[1];
        }
        #pragma unroll
        for (int p = 0; p < 4; p++) {
            int k = tid >> 3, nq = (tid & 7) * 4 + p * 32;
            float4 v = *(const float4*)&W[(size_t)(k0 + k) * N + bn + nq];
            *(__half2*)&Bs[buf][k * BS_STRIDE + nq]     = __floats2half2_rn(v.x, v.y);
            *(__half2*)&Bs[buf][k * BS_STRIDE + nq + 2] = __floats2half2_rn(v.z, v.w);
        }
    };

    auto compute = [&](int buf) {
        #pragma unroll
        for (int kk = 0; kk < BK; kk += 16) {
            uint32_t af[4][4], bf[4][2];
            #pragma unroll
            for (int i = 0; i < 4; i++)
                ldsm4(af[i], s2u(&As[buf][(a_row + i * 16) * AS_STRIDE + kk + a_colh]));
            #pragma unroll
            for (int jp = 0; jp < 2; jp++) {
                uint32_t r[4];
                ldsm4t(r, s2u(&Bs[buf][(kk + b_krow) * BS_STRIDE + wn * 32 + jp * 16 + b_coln]));
                bf[jp * 2][0] = r[0]; bf[jp * 2][1] = r[1];
                bf[jp * 2 + 1][0] = r[2]; bf[jp * 2 + 1][1] = r[3];
            }
            #pragma unroll
            for (int i = 0; i < 4; i++)
                #pragma unroll
                for (int j = 0; j < 4; j++)
                    mma_f16(acc[i][j], af[i], bf[j]);
        }
    };

    int NS = K / BK;
    load_stage(0, 0);
    __syncthreads();
    for (int s = 0; s < NS; s++) {
        if (s + 1 < NS) load_stage(s + 1, (s + 1) & 1);
        compute(s & 1);
        __syncthreads();
    }

    int r0 = bm + wm * 64 + (lane >> 2);
    int c00 = bn + wn * 32 + (lane & 3) * 2;
    #pragma unroll
    for (int i = 0; i < 4; i++) {
        int row = r0 + i * 16;
        #pragma unroll
        for (int j = 0; j < 4; j++) {
            int col = c00 + j * 8;
            float2 bv = *(const float2*)&bias[col];
            float v0 = acc[i][j][0] + bv.x, v1 = acc[i][j][1] + bv.y;
            float v2 = acc[i][j][2] + bv.x, v3 = acc[i][j][3] + bv.y;
            if constexpr (sizeof(OT) == 4) {
                *(float2*)((float*)C + (size_t)row * N + col)       = make_float2(v0, v1);
                *(float2*)((float*)C + (size_t)(row + 8) * N + col) = make_float2(v2, v3);
            } else {
                *(__half2*)((__half*)C + (size_t)row * N + col)       = __floats2half2_rn(v0, v1);
                *(__half2*)((__half*)C + (size_t)(row + 8) * N + col) = __floats2half2_rn(v2, v3);
            }
        }
    }
}

// ---------------------------------------------------------------------------
// RoPE in-place on half q and k.
// ---------------------------------------------------------------------------
__global__ void rope_h(__half* __restrict__ q, __half* __restrict__ k,
                       const float* __restrict__ freqs)
{
    int idx = blockIdx.x * blockDim.x + threadIdx.x;
    const int total = B_ * S_ * H_ * (HD_ / 2);
    __half* p = q;
    int t = idx;
    if (t >= total) { p = k; t -= total; }
    int i = t & 31;
    int h = (t >> 5) & 15;
    int s = (t >> 9) & 2047;
    int b = t >> 20;
    float2 cs = *(const float2*)&freqs[s * 64 + i * 2];
    __half2* addr = (__half2*)&p[(b * S_ + s) * D_ + h * HD_ + 2 * i];
    float2 xv = __half22float2(*addr);
    *addr = __floats2half2_rn(xv.x * cs.x - xv.y * cs.y,
                              xv.x * cs.y + xv.y * cs.x);
}

// ---------------------------------------------------------------------------
// Flash attention, fp16 HMMA. CTA: 64 queries of one (b,h); 4 warps x 16q.
// K/V 64-key tiles in smem; S frags stay in registers -> P frags (no smem trip).
// ---------------------------------------------------------------------------
#define QKV_STRIDE 72   // 64 + 8 pad (144B rows)

__global__ __launch_bounds__(128) void attn_mma(
    const __half* __restrict__ Q, const __half* __restrict__ K,
    const __half* __restrict__ V, __half* __restrict__ O)
{
    __shared__ __align__(16) __half Qs[64 * QKV_STRIDE];
    __shared__ __align__(16) __half Ks[64 * QKV_STRIDE];
    __shared__ __align__(16) __half Vs[64 * QKV_STRIDE];

    int tid = threadIdx.x, lane = tid & 31, wid = tid >> 5;
    int q0 = blockIdx.x * 64, h = blockIdx.y, b = blockIdx.z;
    const size_t base = (size_t)b * S_ * D_ + h * HD_;

    // Load Q tile (row = tid/2, half-row j = tid%2 -> 32 halfs = 4x uint4)
    {
        int row = tid >> 1, j = tid & 1;
        const uint4* src = (const uint4*)(Q + base + (size_t)(q0 + row) * D_ + j * 32);
        uint4* dst = (uint4*)&Qs[row * QKV_STRIDE + j * 32];
        dst[0] = src[0]; dst[1] = src[1]; dst[2] = src[2]; dst[3] = src[3];
    }
    __syncthreads();

    // Q A-frags resident (4 k16 tiles)
    uint32_t aq[4][4];
    {
        int r = wid * 16 + (lane & 15);
        int ch = (lane >> 4) << 3;
        #pragma unroll
        for (int kt = 0; kt < 4; kt++)
            ldsm4(aq[kt], s2u(&Qs[r * QKV_STRIDE + kt * 16 + ch]));
    }

    float of[8][4];
    #pragma unroll
    for (int j = 0; j < 8; j++)
        #pragma unroll
        for (int c = 0; c < 4; c++) of[j][c] = 0.f;
    float m0 = -1e30f, m1 = -1e30f, l0 = 0.f, l1 = 0.f;

    for (int t = 0; t < S_ / 64; t++) {
        __syncthreads();  // previous iter's Ks/Vs reads complete
        {
            int row = tid >> 1, j = tid & 1;
            const uint4* ks = (const uint4*)(K + base + (size_t)(t * 64 + row) * D_ + j * 32);
            uint4* kd = (uint4*)&Ks[row * QKV_STRIDE + j * 32];
            kd[0] = ks[0]; kd[1] = ks[1]; kd[2] = ks[2]; kd[3] = ks[3];
            const uint4* vs = (const uint4*)(V + base + (size_t)(t * 64 + row) * D_ + j * 32);
            uint4* vd = (uint4*)&Vs[row * QKV_STRIDE + j * 32];
            vd[0] = vs[0]; vd[1] = vs[1]; vd[2] = vs[2]; vd[3] = vs[3];
        }
        __syncthreads();

        // S = Q @ K^T  (B frags from Ks[key][d]: non-trans ldmatrix)
        float sf[8][4];
        #pragma unroll
        for (int j = 0; j < 8; j++)
            #pragma unroll
            for (int c = 0; c < 4; c++) sf[j][c] = 0.f;

        #pragma unroll
        for (int kt = 0; kt < 4; kt++) {
            #pragma unroll
            for (int jp = 0; jp < 4; jp++) {
                uint32_t rr[4];
                ldsm4(rr, s2u(&Ks[(jp * 16 + (lane & 15)) * QKV_STRIDE +
                                  kt * 16 + ((lane >> 4) << 3)]));
                uint32_t blo[2] = { rr[0], rr[2] };   // non-trans pairing
                uint32_t bhi[2] = { rr[1], rr[3] };
                mma_f16(sf[jp * 2], aq[kt], blo);
                mma_f16(sf[jp * 2 + 1], aq[kt], bhi);
            }
        }

        // scale
        #pragma unroll
        for (int j = 0; j < 8; j++) {
            sf[j][0] *= 0.125f; sf[j][1] *= 0.125f;
            sf[j][2] *= 0.125f; sf[j][3] *= 0.125f;
        }

        // online softmax, row 0 (frag elems 0,1) with m0/l0
        {
            float mx = -1e30f;
            #pragma unroll
            for (int j = 0; j < 8; j++) mx = fmaxf(mx, fmaxf(sf[j][0], sf[j][1]));
            mx = fmaxf(mx, __shfl_xor_sync(0xffffffffu, mx, 1, 4));
            mx = fmaxf(mx, __shfl_xor_sync(0xffffffffu, mx, 2, 4));
            float mnew = fmaxf(m0, mx);
            float alpha = fexp2((m0 - mnew) * LOG2E);
            float rs = 0.f;
            #pragma unroll
            for (int j = 0; j < 8; j++) {
                float p0 = fexp2((sf[j][0] - mnew) * LOG2E);
                float p1 = fexp2((sf[j][1] - mnew) * LOG2E);
                sf[j][0] = p0; sf[j][1] = p1; rs += p0 + p1;
            }
            rs += __shfl_xor_sync(0xffffffffu, rs, 1, 4);
            rs += __shfl_xor_sync(0xffffffffu, rs, 2, 4);
            l0 = l0 * alpha + rs; m0 = mnew;
            #pragma unroll
            for (int j = 0; j < 8; j++) { of[j][0] *= alpha; of[j][1] *= alpha; }
        }
        // row 1 (frag elems 2,3) with m1/l1
        {
            float mx = -1e30f;
            #pragma unroll
            for (int j = 0; j < 8; j++) mx = fmaxf(mx, fmaxf(sf[j][2], sf[j][3]));
            mx = fmaxf(mx, __shfl_xor_sync(0xffffffffu, mx, 1, 4));
            mx = fmaxf(mx, __shfl_xor_sync(0xffffffffu, mx, 2, 4));
            float mnew = fmaxf(m1, mx);
            float alpha = fexp2((m1 - mnew) * LOG2E);
            float rs = 0.f;
            #pragma unroll
            for (int j = 0; j < 8; j++) {
                float p0 = fexp2((sf[j][2] - mnew) * LOG2E);
                float p1 = fexp2((sf[j][3] - mnew) * LOG2E);
                sf[j][2] = p0; sf[j][3] = p1; rs += p0 + p1;
            }
            rs += __shfl_xor_sync(0xffffffffu, rs, 1, 4);
            rs += __shfl_xor_sync(0xffffffffu, rs, 2, 4);
            l1 = l1 * alpha + rs; m1 = mnew;
            #pragma unroll
            for (int j = 0; j < 8; j++) { of[j][2] *= alpha; of[j][3] *= alpha; }
        }

        // P -> A frags
        uint32_t pa[4][4];
        #pragma unroll
        for (int kk = 0; kk < 4; kk++) {
            pa[kk][0] = pack_h2(sf[2 * kk][0], sf[2 * kk][1]);
            pa[kk][1] = pack_h2(sf[2 * kk][2], sf[2 * kk][3]);
            pa[kk][2] = pack_h2(sf[2 * kk + 1][0], sf[2 * kk + 1][1]);
            pa[kk][3] = pack_h2(sf[2 * kk + 1][2], sf[2 * kk + 1][3]);
        }

        // O += P @ V  (B frags from Vs[key][d]: trans ldmatrix)
        #pragma unroll
        for (int kk = 0; kk < 4; kk++) {
            #pragma unroll
            for (int jp = 0; jp < 4; jp++) {
                uint32_t rr[4];
                ldsm4t(rr, s2u(&Vs[(kk * 16 + (lane & 15)) * QKV_STRIDE +
                                   jp * 16 + ((lane >> 4) << 3)]));
                uint32_t blo[2] = { rr[0], rr[1] };   // trans pairing
                uint32_t bhi[2] = { rr[2], rr[3] };
                mma_f16(of[jp * 2], pa[kk], blo);
                mma_f16(of[jp * 2 + 1], pa[kk], bhi);
            }
        }
    }

    float inv0 = 1.f / l0, inv1 = 1.f / l1;
    int r = wid * 16 + (lane >> 2);
    int c0 = (lane & 3) * 2;
    #pragma unroll
    for (int j = 0; j < 8; j++) {
        int col = j * 8 + c0;
        *(__half2*)(O + base + (size_t)(q0 + r) * D_ + col) =
            __floats2half2_rn(of[j][0] * inv0, of[j][1] * inv0);
        *(__half2*)(O + base + (size_t)(q0 + r + 8) * D_ + col) =
            __floats2half2_rn(of[j][2] * inv1, of[j][3] * inv1);
    }
}

// ---------------------------------------------------------------------------
// Launch
// ---------------------------------------------------------------------------
extern "C" void kernel_launch(void* const* d_in, const int* in_sizes, int n_in,
                              void* d_out, int out_size)
{
    const float* x  = (const float*)d_in[0];
    const float* fr = (const float*)d_in[1];
    const float* wq = (const float*)d_in[2];
    const float* bq = (const float*)d_in[3];
    const float* wk = (const float*)d_in[4];
    const float* bk = (const float*)d_in[5];
    const float* wv = (const float*)d_in[6];
    const float* bv = (const float*)d_in[7];
    const float* wo = (const float*)d_in[8];
    const float* bo = (const float*)d_in[9];
    float* out = (float*)d_out;

    __half *qh, *kh, *vh, *oh;
    cudaGetSymbolAddress((void**)&qh, g_qh);
    cudaGetSymbolAddress((void**)&kh, g_kh);
    cudaGetSymbolAddress((void**)&vh, g_vh);
    cudaGetSymbolAddress((void**)&oh, g_oh);

    dim3 gg(D_ / 128, (B_ * S_) / 128);  // (8, 32)
    gemm_mma<float, __half><<<gg, 256>>>(x, wq, bq, qh, B_ * S_, D_, D_);
    gemm_mma<float, __half><<<gg, 256>>>(x, wk, bk, kh, B_ * S_, D_, D_);
    gemm_mma<float, __half><<<gg, 256>>>(x, wv, bv, vh, B_ * S_, D_, D_);

    int pair_threads = 2 * B_ * S_ * H_ * (HD_ / 2);
    rope_h<<<pair_threads / 256, 256>>>(qh, kh, fr);

    attn_mma<<<dim3(S_ / 64, H_, B_), 128>>>(qh, kh, vh, oh);

    gemm_mma<__half, float><<<gg, 256>>>(oh, wo, bo, out, B_ * S_, D_, D_);
}

// round 4
// speedup vs baseline: 5.4278x; 1.1214x over previous
#include <cuda_runtime.h>
#include <cuda_fp16.h>
#include <math.h>
#include <stdint.h>

#define B_ 2
#define S_ 2048
#define D_ 1024
#define H_ 16
#define HD_ 64
#define LOG2E 1.4426950408889634f

// fp16 scratch (static device globals: allocation-free)
__device__ __half g_xh[B_*S_*D_];
__device__ __half g_wqh[D_*D_];
__device__ __half g_wkh[D_*D_];
__device__ __half g_wvh[D_*D_];
__device__ __half g_woh[D_*D_];
__device__ __half g_qh[B_*S_*D_];
__device__ __half g_kh[B_*S_*D_];
__device__ __half g_vh[B_*S_*D_];
__device__ __half g_oh[B_*S_*D_];

// ---------------------------------------------------------------------------
// helpers
// ---------------------------------------------------------------------------
__device__ __forceinline__ uint32_t s2u(const void* p) {
    return (uint32_t)__cvta_generic_to_shared(p);
}
__device__ __forceinline__ void ldsm4(uint32_t r[4], uint32_t a) {
    asm volatile("ldmatrix.sync.aligned.m8n8.x4.shared.b16 {%0,%1,%2,%3},[%4];\n"
        : "=r"(r[0]), "=r"(r[1]), "=r"(r[2]), "=r"(r[3]) : "r"(a));
}
__device__ __forceinline__ void ldsm4t(uint32_t r[4], uint32_t a) {
    asm volatile("ldmatrix.sync.aligned.m8n8.x4.trans.shared.b16 {%0,%1,%2,%3},[%4];\n"
        : "=r"(r[0]), "=r"(r[1]), "=r"(r[2]), "=r"(r[3]) : "r"(a));
}
__device__ __forceinline__ void mma_f16(float c[4], const uint32_t a[4], const uint32_t b[2]) {
    asm volatile(
        "mma.sync.aligned.m16n8k16.row.col.f32.f16.f16.f32 "
        "{%0,%1,%2,%3},{%4,%5,%6,%7},{%8,%9},{%0,%1,%2,%3};\n"
        : "+f"(c[0]), "+f"(c[1]), "+f"(c[2]), "+f"(c[3])
        : "r"(a[0]), "r"(a[1]), "r"(a[2]), "r"(a[3]), "r"(b[0]), "r"(b[1]));
}
__device__ __forceinline__ uint32_t pack_h2(float a, float b) {
    __half2 h = __floats2half2_rn(a, b);
    return *reinterpret_cast<uint32_t*>(&h);
}
#define CP16(dst, src) \
    asm volatile("cp.async.ca.shared.global [%0], [%1], 16;\n" :: "r"(dst), "l"(src))
#define CP_COMMIT() asm volatile("cp.async.commit_group;\n" ::: "memory")
#define CP_WAIT(n)  asm volatile("cp.async.wait_group " #n ";\n" ::: "memory")

// exp2 on fma/alu pipes, x <= 0 (clamped), |rel err| ~2.4e-6.
__device__ __forceinline__ float fexp2n(float x) {
    x = fmaxf(x, -120.f);
    float r = x + 12582912.f;               // 2^23 + 2^22 magic: int in low bits
    int ir = __float_as_int(r);
    float f = x - (r - 12582912.f);         // [-0.5, 0.5]
    float p = 1.3333558e-3f;
    p = fmaf(p, f, 9.6181291e-3f);
    p = fmaf(p, f, 5.5504109e-2f);
    p = fmaf(p, f, 2.4022651e-1f);
    p = fmaf(p, f, 6.9314718e-1f);
    p = fmaf(p, f, 1.0f);
    return __int_as_float(__float_as_int(p) + (ir << 23));
}

// ---------------------------------------------------------------------------
// fp32 -> fp16 convert (n multiple of 4)
// ---------------------------------------------------------------------------
__global__ void f2h(const float* __restrict__ s, __half* __restrict__ d, int n) {
    int i = (blockIdx.x * blockDim.x + threadIdx.x) * 4;
    if (i < n) {
        float4 v = *(const float4*)(s + i);
        *(__half2*)(d + i)     = __floats2half2_rn(v.x, v.y);
        *(__half2*)(d + i + 2) = __floats2half2_rn(v.z, v.w);
    }
}

// ---------------------------------------------------------------------------
// GEMM: C[M,N] = A[M,K] @ W[K,N] + bias, A/W fp16, optional fused RoPE.
// Block 128x128, BK=32, 4-stage cp.async, 8 warps (2m x 4n), HMMA fp32-accum.
// ---------------------------------------------------------------------------
#define BK 32
#define AS_STRIDE 40    // 32 + 8 pad halfs (80B rows)
#define BS_STRIDE 136   // 128 + 8 pad halfs (272B rows)
#define A_ST_SZ (128 * AS_STRIDE)
#define B_ST_SZ (BK * BS_STRIDE)
#define GEMM_SMEM ((4 * (A_ST_SZ + B_ST_SZ)) * 2)

template<bool ROPE, typename OT>
__global__ __launch_bounds__(256) void gemm_cp(
    const __half* __restrict__ A, const __half* __restrict__ W,
    const float* __restrict__ bias, const float* __restrict__ freqs,
    OT* __restrict__ C, int M, int N, int K)
{
    extern __shared__ __half sm[];
    __half* As = sm;                    // [4][A_ST_SZ]
    __half* Bs = sm + 4 * A_ST_SZ;      // [4][B_ST_SZ]

    int tid = threadIdx.x, lane = tid & 31, wid = tid >> 5;
    int wm = wid & 1, wn = wid >> 1;
    int bm = blockIdx.y * 128, bn = blockIdx.x * 128;

    float acc[4][4][4];
    #pragma unroll
    for (int i = 0; i < 4; i++)
        #pragma unroll
        for (int j = 0; j < 4; j++)
            #pragma unroll
            for (int c = 0; c < 4; c++) acc[i][j][c] = 0.f;

    // cp.async chunk mapping (16B = 8 halfs)
    int ac0 = tid * 2;                       // A: 512 chunks, 2/thread
    int a_r0 = ac0 >> 2, a_o0 = (ac0 & 3) * 8;
    int a_r1 = (ac0 + 1) >> 2, a_o1 = ((ac0 + 1) & 3) * 8;
    int bc0 = tid * 2;                       // B: 512 chunks, 2/thread
    int b_r0 = bc0 >> 4, b_o0 = (bc0 & 15) * 8;
    int b_r1 = (bc0 + 1) >> 4, b_o1 = ((bc0 + 1) & 15) * 8;

    auto load_stage = [&](int s, int buf) {
        int k0 = s * BK;
        __half* ab = As + buf * A_ST_SZ;
        __half* bb = Bs + buf * B_ST_SZ;
        CP16(s2u(ab + a_r0 * AS_STRIDE + a_o0),
             A + (size_t)(bm + a_r0) * K + k0 + a_o0);
        CP16(s2u(ab + a_r1 * AS_STRIDE + a_o1),
             A + (size_t)(bm + a_r1) * K + k0 + a_o1);
        CP16(s2u(bb + b_r0 * BS_STRIDE + b_o0),
             W + (size_t)(k0 + b_r0) * N + bn + b_o0);
        CP16(s2u(bb + b_r1 * BS_STRIDE + b_o1),
             W + (size_t)(k0 + b_r1) * N + bn + b_o1);
    };

    int a_row = wm * 64 + (lane & 15);
    int a_colh = (lane >> 4) << 3;
    int b_krow = lane & 15;
    int b_coln = (lane >> 4) << 3;

    auto compute = [&](int buf) {
        const __half* ab = As + buf * A_ST_SZ;
        const __half* bb = Bs + buf * B_ST_SZ;
        #pragma unroll
        for (int kk = 0; kk < BK; kk += 16) {
            uint32_t af[4][4], bf[4][2];
            #pragma unroll
            for (int i = 0; i < 4; i++)
                ldsm4(af[i], s2u(ab + (a_row + i * 16) * AS_STRIDE + kk + a_colh));
            #pragma unroll
            for (int jp = 0; jp < 2; jp++) {
                uint32_t r[4];
                ldsm4t(r, s2u(bb + (kk + b_krow) * BS_STRIDE + wn * 32 + jp * 16 + b_coln));
                bf[jp * 2][0] = r[0]; bf[jp * 2][1] = r[1];
                bf[jp * 2 + 1][0] = r[2]; bf[jp * 2 + 1][1] = r[3];
            }
            #pragma unroll
            for (int i = 0; i < 4; i++)
                #pragma unroll
                for (int j = 0; j < 4; j++)
                    mma_f16(acc[i][j], af[i], bf[j]);
        }
    };

    const int NS = K / BK;   // 32
    load_stage(0, 0); CP_COMMIT();
    load_stage(1, 1); CP_COMMIT();
    load_stage(2, 2); CP_COMMIT();

    for (int s = 0; s < NS; s++) {
        CP_WAIT(2);
        __syncthreads();
        compute(s & 3);
        if (s + 3 < NS) load_stage(s + 3, (s + 3) & 3);
        CP_COMMIT();
    }

    int r0 = bm + wm * 64 + (lane >> 2);
    int c00 = bn + wn * 32 + (lane & 3) * 2;
    #pragma unroll
    for (int i = 0; i < 4; i++) {
        int row = r0 + i * 16;
        #pragma unroll
        for (int j = 0; j < 4; j++) {
            int col = c00 + j * 8;
            float2 bv = *(const float2*)&bias[col];
            float v0 = acc[i][j][0] + bv.x, v1 = acc[i][j][1] + bv.y;
            float v2 = acc[i][j][2] + bv.x, v3 = acc[i][j][3] + bv.y;
            if (ROPE) {
                int hp = col & 63;  // even pair base within head
                float2 c1 = *(const float2*)&freqs[(row & (S_ - 1)) * 64 + hp];
                float2 c2 = *(const float2*)&freqs[((row + 8) & (S_ - 1)) * 64 + hp];
                float t0 = v0 * c1.x - v1 * c1.y;
                float t1 = v0 * c1.y + v1 * c1.x;
                float t2 = v2 * c2.x - v3 * c2.y;
                float t3 = v2 * c2.y + v3 * c2.x;
                v0 = t0; v1 = t1; v2 = t2; v3 = t3;
            }
            if (sizeof(OT) == 4) {
                *(float2*)((float*)C + (size_t)row * N + col)       = make_float2(v0, v1);
                *(float2*)((float*)C + (size_t)(row + 8) * N + col) = make_float2(v2, v3);
            } else {
                *(__half2*)((__half*)C + (size_t)row * N + col)       = __floats2half2_rn(v0, v1);
                *(__half2*)((__half*)C + (size_t)(row + 8) * N + col) = __floats2half2_rn(v2, v3);
            }
        }
    }
}

// ---------------------------------------------------------------------------
// Flash attention, fp16 HMMA. CTA: 128 queries of one (b,h); 8 warps x 16q.
// cp.async double-buffered 64-key K/V tiles; softmax scale folded into exp arg.
// ---------------------------------------------------------------------------
#define QKV_STRIDE 72   // 64 + 8 pad halfs (144B rows)
#define Q_SZ (128 * QKV_STRIDE)
#define KV_SZ (64 * QKV_STRIDE)
#define ATTN_SMEM ((Q_SZ + 4 * KV_SZ) * 2)

__global__ __launch_bounds__(256) void attn_mma(
    const __half* __restrict__ Q, const __half* __restrict__ K,
    const __half* __restrict__ V, __half* __restrict__ O)
{
    extern __shared__ __half asm_[];
    __half* Qs = asm_;                  // [128][72]
    __half* Ks = asm_ + Q_SZ;           // [2][64][72]
    __half* Vs = asm_ + Q_SZ + 2 * KV_SZ;

    int tid = threadIdx.x, lane = tid & 31, wid = tid >> 5;
    int q0 = blockIdx.x * 128, h = blockIdx.y, b = blockIdx.z;
    const size_t base = (size_t)b * S_ * D_ + h * HD_;

    // Q: 128 rows x 8 chunks = 1024 chunks, 4/thread
    #pragma unroll
    for (int p = 0; p < 4; p++) {
        int c = tid + p * 256;
        int row = c >> 3, off = (c & 7) * 8;
        CP16(s2u(Qs + row * QKV_STRIDE + off),
             Q + base + (size_t)(q0 + row) * D_ + off);
    }
    CP_COMMIT();

    auto load_kv = [&](int t, int buf) {
        __half* kb = Ks + buf * KV_SZ;
        __half* vb = Vs + buf * KV_SZ;
        #pragma unroll
        for (int p = 0; p < 4; p++) {
            int c = tid + p * 256;          // 0..1023; K first 512, V next
            int row = (c >> 3) & 63, off = (c & 7) * 8;
            if (c < 512)
                CP16(s2u(kb + row * QKV_STRIDE + off),
                     K + base + (size_t)(t * 64 + row) * D_ + off);
            else
                CP16(s2u(vb + row * QKV_STRIDE + off),
                     V + base + (size_t)(t * 64 + row) * D_ + off);
        }
    };
    load_kv(0, 0); CP_COMMIT();

    CP_WAIT(1);   // Q arrived
    __syncthreads();

    uint32_t aq[4][4];
    {
        int r = wid * 16 + (lane & 15);
        int ch = (lane >> 4) << 3;
        #pragma unroll
        for (int kt = 0; kt < 4; kt++)
            ldsm4(aq[kt], s2u(Qs + r * QKV_STRIDE + kt * 16 + ch));
    }

    float of[8][4];
    #pragma unroll
    for (int j = 0; j < 8; j++)
        #pragma unroll
        for (int c = 0; c < 4; c++) of[j][c] = 0.f;
    float m0 = -1e30f, m1 = -1e30f, l0 = 0.f, l1 = 0.f;
    const float cs_ = 0.125f * LOG2E;     // fold score scale into exp2 arg

    for (int t = 0; t < S_ / 64; t++) {
        CP_WAIT(0);          // stage t resident
        __syncthreads();
        if (t + 1 < S_ / 64) load_kv(t + 1, (t + 1) & 1);
        CP_COMMIT();

        const __half* kb = Ks + (t & 1) * KV_SZ;
        const __half* vb = Vs + (t & 1) * KV_SZ;

        // S = Q @ K^T (raw, unscaled)
        float sf[8][4];
        #pragma unroll
        for (int j = 0; j < 8; j++)
            #pragma unroll
            for (int c = 0; c < 4; c++) sf[j][c] = 0.f;

        #pragma unroll
        for (int kt = 0; kt < 4; kt++) {
            #pragma unroll
            for (int jp = 0; jp < 4; jp++) {
                uint32_t rr[4];
                ldsm4(rr, s2u(kb + (jp * 16 + (lane & 15)) * QKV_STRIDE +
                              kt * 16 + ((lane >> 4) << 3)));
                uint32_t blo[2] = { rr[0], rr[2] };
                uint32_t bhi[2] = { rr[1], rr[3] };
                mma_f16(sf[jp * 2], aq[kt], blo);
                mma_f16(sf[jp * 2 + 1], aq[kt], bhi);
            }
        }

        // online softmax, row 0 (elems 0,1)
        {
            float mx = -1e30f;
            #pragma unroll
            for (int j = 0; j < 8; j++) mx = fmaxf(mx, fmaxf(sf[j][0], sf[j][1]));
            mx = fmaxf(mx, __shfl_xor_sync(0xffffffffu, mx, 1, 4));
            mx = fmaxf(mx, __shfl_xor_sync(0xffffffffu, mx, 2, 4));
            float mnew = fmaxf(m0, mx);
            float nmc = -mnew * cs_;
            float alpha = fexp2n(fmaf(m0, cs_, nmc));
            float rs = 0.f;
            #pragma unroll
            for (int j = 0; j < 8; j++) {
                float p0 = fexp2n(fmaf(sf[j][0], cs_, nmc));
                float p1 = fexp2n(fmaf(sf[j][1], cs_, nmc));
                sf[j][0] = p0; sf[j][1] = p1; rs += p0 + p1;
            }
            rs += __shfl_xor_sync(0xffffffffu, rs, 1, 4);
            rs += __shfl_xor_sync(0xffffffffu, rs, 2, 4);
            l0 = l0 * alpha + rs; m0 = mnew;
            #pragma unroll
            for (int j = 0; j < 8; j++) { of[j][0] *= alpha; of[j][1] *= alpha; }
        }
        // row 1 (elems 2,3)
        {
            float mx = -1e30f;
            #pragma unroll
            for (int j = 0; j < 8; j++) mx = fmaxf(mx, fmaxf(sf[j][2], sf[j][3]));
            mx = fmaxf(mx, __shfl_xor_sync(0xffffffffu, mx, 1, 4));
            mx = fmaxf(mx, __shfl_xor_sync(0xffffffffu, mx, 2, 4));
            float mnew = fmaxf(m1, mx);
            float nmc = -mnew * cs_;
            float alpha = fexp2n(fmaf(m1, cs_, nmc));
            float rs = 0.f;
            #pragma unroll
            for (int j = 0; j < 8; j++) {
                float p0 = fexp2n(fmaf(sf[j][2], cs_, nmc));
                float p1 = fexp2n(fmaf(sf[j][3], cs_, nmc));
                sf[j][2] = p0; sf[j][3] = p1; rs += p0 + p1;
            }
            rs += __shfl_xor_sync(0xffffffffu, rs, 1, 4);
            rs += __shfl_xor_sync(0xffffffffu, rs, 2, 4);
            l1 = l1 * alpha + rs; m1 = mnew;
            #pragma unroll
            for (int j = 0; j < 8; j++) { of[j][2] *= alpha; of[j][3] *= alpha; }
        }

        // P -> A frags
        uint32_t pa[4][4];
        #pragma unroll
        for (int kk = 0; kk < 4; kk++) {
            pa[kk][0] = pack_h2(sf[2 * kk][0], sf[2 * kk][1]);
            pa[kk][1] = pack_h2(sf[2 * kk][2], sf[2 * kk][3]);
            pa[kk][2] = pack_h2(sf[2 * kk + 1][0], sf[2 * kk + 1][1]);
            pa[kk][3] = pack_h2(sf[2 * kk + 1][2], sf[2 * kk + 1][3]);
        }

        // O += P @ V
        #pragma unroll
        for (int kk = 0; kk < 4; kk++) {
            #pragma unroll
            for (int jp = 0; jp < 4; jp++) {
                uint32_t rr[4];
                ldsm4t(rr, s2u(vb + (kk * 16 + (lane & 15)) * QKV_STRIDE +
                               jp * 16 + ((lane >> 4) << 3)));
                uint32_t blo[2] = { rr[0], rr[1] };
                uint32_t bhi[2] = { rr[2], rr[3] };
                mma_f16(of[jp * 2], pa[kk], blo);
                mma_f16(of[jp * 2 + 1], pa[kk], bhi);
            }
        }
    }

    float inv0 = 1.f / l0, inv1 = 1.f / l1;
    int r = wid * 16 + (lane >> 2);
    int c0 = (lane & 3) * 2;
    #pragma unroll
    for (int j = 0; j < 8; j++) {
        int col = j * 8 + c0;
        *(__half2*)(O + base + (size_t)(q0 + r) * D_ + col) =
            __floats2half2_rn(of[j][0] * inv0, of[j][1] * inv0);
        *(__half2*)(O + base + (size_t)(q0 + r + 8) * D_ + col) =
            __floats2half2_rn(of[j][2] * inv1, of[j][3] * inv1);
    }
}

// ---------------------------------------------------------------------------
// Launch
// ---------------------------------------------------------------------------
extern "C" void kernel_launch(void* const* d_in, const int* in_sizes, int n_in,
                              void* d_out, int out_size)
{
    const float* x  = (const float*)d_in[0];
    const float* fr = (const float*)d_in[1];
    const float* wq = (const float*)d_in[2];
    const float* bq = (const float*)d_in[3];
    const float* wk = (const float*)d_in[4];
    const float* bk = (const float*)d_in[5];
    const float* wv = (const float*)d_in[6];
    const float* bv = (const float*)d_in[7];
    const float* wo = (const float*)d_in[8];
    const float* bo = (const float*)d_in[9];
    float* out = (float*)d_out;

    __half *xh, *wqh, *wkh, *wvh, *woh, *qh, *kh, *vh, *oh;
    cudaGetSymbolAddress((void**)&xh,  g_xh);
    cudaGetSymbolAddress((void**)&wqh, g_wqh);
    cudaGetSymbolAddress((void**)&wkh, g_wkh);
    cudaGetSymbolAddress((void**)&wvh, g_wvh);
    cudaGetSymbolAddress((void**)&woh, g_woh);
    cudaGetSymbolAddress((void**)&qh,  g_qh);
    cudaGetSymbolAddress((void**)&kh,  g_kh);
    cudaGetSymbolAddress((void**)&vh,  g_vh);
    cudaGetSymbolAddress((void**)&oh,  g_oh);

    cudaFuncSetAttribute(gemm_cp<true, __half>,
                         cudaFuncAttributeMaxDynamicSharedMemorySize, GEMM_SMEM);
    cudaFuncSetAttribute(gemm_cp<false, __half>,
                         cudaFuncAttributeMaxDynamicSharedMemorySize, GEMM_SMEM);
    cudaFuncSetAttribute(gemm_cp<false, float>,
                         cudaFuncAttributeMaxDynamicSharedMemorySize, GEMM_SMEM);
    cudaFuncSetAttribute(attn_mma,
                         cudaFuncAttributeMaxDynamicSharedMemorySize, ATTN_SMEM);

    const int NX = B_ * S_ * D_, NW = D_ * D_;
    f2h<<<NX / 1024, 256>>>(x, xh, NX);
    f2h<<<NW / 1024, 256>>>(wq, wqh, NW);
    f2h<<<NW / 1024, 256>>>(wk, wkh, NW);
    f2h<<<NW / 1024, 256>>>(wv, wvh, NW);
    f2h<<<NW / 1024, 256>>>(wo, woh, NW);

    dim3 gg(D_ / 128, (B_ * S_) / 128);  // (8, 32)
    gemm_cp<true,  __half><<<gg, 256, GEMM_SMEM>>>(xh, wqh, bq, fr, qh, B_*S_, D_, D_);
    gemm_cp<true,  __half><<<gg, 256, GEMM_SMEM>>>(xh, wkh, bk, fr, kh, B_*S_, D_, D_);
    gemm_cp<false, __half><<<gg, 256, GEMM_SMEM>>>(xh, wvh, bv, fr, vh, B_*S_, D_, D_);

    attn_mma<<<dim3(S_ / 128, H_, B_), 256, ATTN_SMEM>>>(qh, kh, vh, oh);

    gemm_cp<false, float><<<gg, 256, GEMM_SMEM>>>(oh, woh, bo, fr, out, B_*S_, D_, D_);
}

// round 6
// speedup vs baseline: 6.0981x; 1.1235x over previous
#include <cuda_runtime.h>
#include <cuda_fp16.h>
#include <math.h>
#include <stdint.h>

#define B_ 2
#define S_ 2048
#define D_ 1024
#define H_ 16
#define HD_ 64
#define LOG2E 1.4426950408889634f

// fp16 scratch (static device globals: allocation-free)
__device__ __half g_xh[B_*S_*D_];
__device__ __half g_wqh[D_*D_];
__device__ __half g_wkh[D_*D_];
__device__ __half g_wvh[D_*D_];
__device__ __half g_woh[D_*D_];
__device__ __half g_qh[B_*S_*D_];
__device__ __half g_kh[B_*S_*D_];
__device__ __half g_vh[B_*S_*D_];
__device__ __half g_oh[B_*S_*D_];

// ---------------------------------------------------------------------------
// helpers
// ---------------------------------------------------------------------------
__device__ __forceinline__ uint32_t s2u(const void* p) {
    return (uint32_t)__cvta_generic_to_shared(p);
}
__device__ __forceinline__ void ldsm4(uint32_t r[4], uint32_t a) {
    asm volatile("ldmatrix.sync.aligned.m8n8.x4.shared.b16 {%0,%1,%2,%3},[%4];\n"
        : "=r"(r[0]), "=r"(r[1]), "=r"(r[2]), "=r"(r[3]) : "r"(a));
}
__device__ __forceinline__ void ldsm4t(uint32_t r[4], uint32_t a) {
    asm volatile("ldmatrix.sync.aligned.m8n8.x4.trans.shared.b16 {%0,%1,%2,%3},[%4];\n"
        : "=r"(r[0]), "=r"(r[1]), "=r"(r[2]), "=r"(r[3]) : "r"(a));
}
__device__ __forceinline__ void mma_f16(float c[4], const uint32_t a[4], const uint32_t b[2]) {
    asm volatile(
        "mma.sync.aligned.m16n8k16.row.col.f32.f16.f16.f32 "
        "{%0,%1,%2,%3},{%4,%5,%6,%7},{%8,%9},{%0,%1,%2,%3};\n"
        : "+f"(c[0]), "+f"(c[1]), "+f"(c[2]), "+f"(c[3])
        : "r"(a[0]), "r"(a[1]), "r"(a[2]), "r"(a[3]), "r"(b[0]), "r"(b[1]));
}
__device__ __forceinline__ uint32_t pack_h2(float a, float b) {
    __half2 h = __floats2half2_rn(a, b);
    return *reinterpret_cast<uint32_t*>(&h);
}
// MUFU exp2 (parallel pipe to FMA/tensor)
__device__ __forceinline__ float ex2f(float x) {
    float y;
    asm("ex2.approx.ftz.f32 %0,%1;" : "=f"(y) : "f"(x));
    return y;
}
#define CP16(dst, src) \
    asm volatile("cp.async.ca.shared.global [%0], [%1], 16;\n" :: "r"(dst), "l"(src))
#define CP_COMMIT() asm volatile("cp.async.commit_group;\n" ::: "memory")
#define CP_WAIT(n)  asm volatile("cp.async.wait_group " #n ";\n" ::: "memory")

// ---------------------------------------------------------------------------
// fp32 -> fp16 convert (n multiple of 4)
// ---------------------------------------------------------------------------
__global__ void f2h(const float* __restrict__ s, __half* __restrict__ d, int n) {
    int i = (blockIdx.x * blockDim.x + threadIdx.x) * 4;
    if (i < n) {
        float4 v = *(const float4*)(s + i);
        *(__half2*)(d + i)     = __floats2half2_rn(v.x, v.y);
        *(__half2*)(d + i + 2) = __floats2half2_rn(v.z, v.w);
    }
}

// ---------------------------------------------------------------------------
// GEMM: C[M,N] = A[M,K] @ W[K,N] + bias, A/W fp16, optional fused RoPE.
// Block 128x128, BK=32, 4-stage cp.async, 8 warps (2m x 4n), HMMA fp32-accum.
// ---------------------------------------------------------------------------
#define BK 32
#define AS_STRIDE 40    // 32 + 8 pad halfs (80B rows)
#define BS_STRIDE 136   // 128 + 8 pad halfs (272B rows)
#define A_ST_SZ (128 * AS_STRIDE)
#define B_ST_SZ (BK * BS_STRIDE)
#define GEMM_SMEM ((4 * (A_ST_SZ + B_ST_SZ)) * 2)

template<bool ROPE, typename OT>
__global__ __launch_bounds__(256) void gemm_cp(
    const __half* __restrict__ A, const __half* __restrict__ W,
    const float* __restrict__ bias, const float* __restrict__ freqs,
    OT* __restrict__ C, int M, int N, int K)
{
    extern __shared__ __half sm[];
    __half* As = sm;                    // [4][A_ST_SZ]
    __half* Bs = sm + 4 * A_ST_SZ;      // [4][B_ST_SZ]

    int tid = threadIdx.x, lane = tid & 31, wid = tid >> 5;
    int wm = wid & 1, wn = wid >> 1;
    int bm = blockIdx.y * 128, bn = blockIdx.x * 128;

    float acc[4][4][4];
    #pragma unroll
    for (int i = 0; i < 4; i++)
        #pragma unroll
        for (int j = 0; j < 4; j++)
            #pragma unroll
            for (int c = 0; c < 4; c++) acc[i][j][c] = 0.f;

    int ac0 = tid * 2;
    int a_r0 = ac0 >> 2, a_o0 = (ac0 & 3) * 8;
    int a_r1 = (ac0 + 1) >> 2, a_o1 = ((ac0 + 1) & 3) * 8;
    int bc0 = tid * 2;
    int b_r0 = bc0 >> 4, b_o0 = (bc0 & 15) * 8;
    int b_r1 = (bc0 + 1) >> 4, b_o1 = ((bc0 + 1) & 15) * 8;

    auto load_stage = [&](int s, int buf) {
        int k0 = s * BK;
        __half* ab = As + buf * A_ST_SZ;
        __half* bb = Bs + buf * B_ST_SZ;
        CP16(s2u(ab + a_r0 * AS_STRIDE + a_o0),
             A + (size_t)(bm + a_r0) * K + k0 + a_o0);
        CP16(s2u(ab + a_r1 * AS_STRIDE + a_o1),
             A + (size_t)(bm + a_r1) * K + k0 + a_o1);
        CP16(s2u(bb + b_r0 * BS_STRIDE + b_o0),
             W + (size_t)(k0 + b_r0) * N + bn + b_o0);
        CP16(s2u(bb + b_r1 * BS_STRIDE + b_o1),
             W + (size_t)(k0 + b_r1) * N + bn + b_o1);
    };

    int a_row = wm * 64 + (lane & 15);
    int a_colh = (lane >> 4) << 3;
    int b_krow = lane & 15;
    int b_coln = (lane >> 4) << 3;

    auto compute = [&](int buf) {
        const __half* ab = As + buf * A_ST_SZ;
        const __half* bb = Bs + buf * B_ST_SZ;
        #pragma unroll
        for (int kk = 0; kk < BK; kk += 16) {
            uint32_t af[4][4], bf[4][2];
            #pragma unroll
            for (int i = 0; i < 4; i++)
                ldsm4(af[i], s2u(ab + (a_row + i * 16) * AS_STRIDE + kk + a_colh));
            #pragma unroll
            for (int jp = 0; jp < 2; jp++) {
                uint32_t r[4];
                ldsm4t(r, s2u(bb + (kk + b_krow) * BS_STRIDE + wn * 32 + jp * 16 + b_coln));
                bf[jp * 2][0] = r[0]; bf[jp * 2][1] = r[1];
                bf[jp * 2 + 1][0] = r[2]; bf[jp * 2 + 1][1] = r[3];
            }
            #pragma unroll
            for (int i = 0; i < 4; i++)
                #pragma unroll
                for (int j = 0; j < 4; j++)
                    mma_f16(acc[i][j], af[i], bf[j]);
        }
    };

    const int NS = K / BK;   // 32
    load_stage(0, 0); CP_COMMIT();
    load_stage(1, 1); CP_COMMIT();
    load_stage(2, 2); CP_COMMIT();

    for (int s = 0; s < NS; s++) {
        CP_WAIT(2);
        __syncthreads();
        compute(s & 3);
        if (s + 3 < NS) load_stage(s + 3, (s + 3) & 3);
        CP_COMMIT();
    }

    int r0 = bm + wm * 64 + (lane >> 2);
    int c00 = bn + wn * 32 + (lane & 3) * 2;
    #pragma unroll
    for (int i = 0; i < 4; i++) {
        int row = r0 + i * 16;
        #pragma unroll
        for (int j = 0; j < 4; j++) {
            int col = c00 + j * 8;
            float2 bv = *(const float2*)&bias[col];
            float v0 = acc[i][j][0] + bv.x, v1 = acc[i][j][1] + bv.y;
            float v2 = acc[i][j][2] + bv.x, v3 = acc[i][j][3] + bv.y;
            if (ROPE) {
                int hp = col & 63;
                float2 c1 = *(const float2*)&freqs[(row & (S_ - 1)) * 64 + hp];
                float2 c2 = *(const float2*)&freqs[((row + 8) & (S_ - 1)) * 64 + hp];
                float t0 = v0 * c1.x - v1 * c1.y;
                float t1 = v0 * c1.y + v1 * c1.x;
                float t2 = v2 * c2.x - v3 * c2.y;
                float t3 = v2 * c2.y + v3 * c2.x;
                v0 = t0; v1 = t1; v2 = t2; v3 = t3;
            }
            if (sizeof(OT) == 4) {
                *(float2*)((float*)C + (size_t)row * N + col)       = make_float2(v0, v1);
                *(float2*)((float*)C + (size_t)(row + 8) * N + col) = make_float2(v2, v3);
            } else {
                *(__half2*)((__half*)C + (size_t)row * N + col)       = __floats2half2_rn(v0, v1);
                *(__half2*)((__half*)C + (size_t)(row + 8) * N + col) = __floats2half2_rn(v2, v3);
            }
        }
    }
}

// ---------------------------------------------------------------------------
// Flash attention, fp16 HMMA. CTA: 128 queries of one (b,h); 8 warps x 16q.
// cp.async double-buffered K/V; MUFU exp softmax; row-sums via ones-MMA.
// ---------------------------------------------------------------------------
#define QKV_STRIDE 72
#define Q_SZ (128 * QKV_STRIDE)
#define KV_SZ (64 * QKV_STRIDE)
#define ATTN_SMEM ((Q_SZ + 4 * KV_SZ) * 2)

__global__ __launch_bounds__(256) void attn_mma(
    const __half* __restrict__ Q, const __half* __restrict__ K,
    const __half* __restrict__ V, __half* __restrict__ O)
{
    extern __shared__ __half asm_[];
    __half* Qs = asm_;
    __half* Ks = asm_ + Q_SZ;
    __half* Vs = asm_ + Q_SZ + 2 * KV_SZ;

    int tid = threadIdx.x, lane = tid & 31, wid = tid >> 5;
    int q0 = blockIdx.x * 128, h = blockIdx.y, b = blockIdx.z;
    const size_t base = (size_t)b * S_ * D_ + h * HD_;

    #pragma unroll
    for (int p = 0; p < 4; p++) {
        int c = tid + p * 256;
        int row = c >> 3, off = (c & 7) * 8;
        CP16(s2u(Qs + row * QKV_STRIDE + off),
             Q + base + (size_t)(q0 + row) * D_ + off);
    }
    CP_COMMIT();

    auto load_kv = [&](int t, int buf) {
        __half* kb = Ks + buf * KV_SZ;
        __half* vb = Vs + buf * KV_SZ;
        #pragma unroll
        for (int p = 0; p < 4; p++) {
            int c = tid + p * 256;
            int row = (c >> 3) & 63, off = (c & 7) * 8;
            if (c < 512)
                CP16(s2u(kb + row * QKV_STRIDE + off),
                     K + base + (size_t)(t * 64 + row) * D_ + off);
            else
                CP16(s2u(vb + row * QKV_STRIDE + off),
                     V + base + (size_t)(t * 64 + row) * D_ + off);
        }
    };
    load_kv(0, 0); CP_COMMIT();

    CP_WAIT(1);
    __syncthreads();

    uint32_t aq[4][4];
    {
        int r = wid * 16 + (lane & 15);
        int ch = (lane >> 4) << 3;
        #pragma unroll
        for (int kt = 0; kt < 4; kt++)
            ldsm4(aq[kt], s2u(Qs + r * QKV_STRIDE + kt * 16 + ch));
    }

    float of[8][4];
    #pragma unroll
    for (int j = 0; j < 8; j++)
        #pragma unroll
        for (int c = 0; c < 4; c++) of[j][c] = 0.f;
    float m0 = -1e30f, m1 = -1e30f, l0 = 0.f, l1 = 0.f;
    const float cs_ = 0.125f * LOG2E;
    const uint32_t ones2 = 0x3C003C00u;          // half2(1,1)
    const uint32_t ob[2] = { ones2, ones2 };

    for (int t = 0; t < S_ / 64; t++) {
        CP_WAIT(0);
        __syncthreads();
        if (t + 1 < S_ / 64) load_kv(t + 1, (t + 1) & 1);
        CP_COMMIT();

        const __half* kb = Ks + (t & 1) * KV_SZ;
        const __half* vb = Vs + (t & 1) * KV_SZ;

        // S = Q @ K^T (raw scores)
        float sf[8][4];
        #pragma unroll
        for (int j = 0; j < 8; j++)
            #pragma unroll
            for (int c = 0; c < 4; c++) sf[j][c] = 0.f;

        #pragma unroll
        for (int kt = 0; kt < 4; kt++) {
            #pragma unroll
            for (int jp = 0; jp < 4; jp++) {
                uint32_t rr[4];
                ldsm4(rr, s2u(kb + (jp * 16 + (lane & 15)) * QKV_STRIDE +
                              kt * 16 + ((lane >> 4) << 3)));
                uint32_t blo[2] = { rr[0], rr[2] };
                uint32_t bhi[2] = { rr[1], rr[3] };
                mma_f16(sf[jp * 2], aq[kt], blo);
                mma_f16(sf[jp * 2 + 1], aq[kt], bhi);
            }
        }

        // tile maxima (quad reduce over 4 col-threads)
        float mx0 = -1e30f, mx1 = -1e30f;
        #pragma unroll
        for (int j = 0; j < 8; j++) {
            mx0 = fmaxf(mx0, fmaxf(sf[j][0], sf[j][1]));
            mx1 = fmaxf(mx1, fmaxf(sf[j][2], sf[j][3]));
        }
        mx0 = fmaxf(mx0, __shfl_xor_sync(0xffffffffu, mx0, 1, 4));
        mx0 = fmaxf(mx0, __shfl_xor_sync(0xffffffffu, mx0, 2, 4));
        mx1 = fmaxf(mx1, __shfl_xor_sync(0xffffffffu, mx1, 1, 4));
        mx1 = fmaxf(mx1, __shfl_xor_sync(0xffffffffu, mx1, 2, 4));

        // rescale only when running max changes (quad-uniform branch)
        if (mx0 > m0) {
            float alpha = ex2f((m0 - mx0) * cs_);
            m0 = mx0; l0 *= alpha;
            #pragma unroll
            for (int j = 0; j < 8; j++) { of[j][0] *= alpha; of[j][1] *= alpha; }
        }
        if (mx1 > m1) {
            float alpha = ex2f((m1 - mx1) * cs_);
            m1 = mx1; l1 *= alpha;
            #pragma unroll
            for (int j = 0; j < 8; j++) { of[j][2] *= alpha; of[j][3] *= alpha; }
        }

        // P = exp(scores) via MUFU, packed straight to fp16 A-frags
        float nm0 = -m0 * cs_, nm1 = -m1 * cs_;
        uint32_t pa[4][4];
        #pragma unroll
        for (int kk = 0; kk < 4; kk++) {
            int ja = 2 * kk, jb = 2 * kk + 1;
            float a0 = ex2f(fmaf(sf[ja][0], cs_, nm0));
            float a1 = ex2f(fmaf(sf[ja][1], cs_, nm0));
            float a2 = ex2f(fmaf(sf[ja][2], cs_, nm1));
            float a3 = ex2f(fmaf(sf[ja][3], cs_, nm1));
            float b0 = ex2f(fmaf(sf[jb][0], cs_, nm0));
            float b1 = ex2f(fmaf(sf[jb][1], cs_, nm0));
            float b2 = ex2f(fmaf(sf[jb][2], cs_, nm1));
            float b3 = ex2f(fmaf(sf[jb][3], cs_, nm1));
            pa[kk][0] = pack_h2(a0, a1);
            pa[kk][1] = pack_h2(a2, a3);
            pa[kk][2] = pack_h2(b0, b1);
            pa[kk][3] = pack_h2(b2, b3);
        }

        // row sums l += P @ ones  (tensor core, fp32 accum, matches fp16 P)
        float lacc[4] = { 0.f, 0.f, 0.f, 0.f };
        #pragma unroll
        for (int kk = 0; kk < 4; kk++)
            mma_f16(lacc, pa[kk], ob);
        l0 += lacc[0];
        l1 += lacc[2];

        // O += P @ V
        #pragma unroll
        for (int kk = 0; kk < 4; kk++) {
            #pragma unroll
            for (int jp = 0; jp < 4; jp++) {
                uint32_t rr[4];
                ldsm4t(rr, s2u(vb + (kk * 16 + (lane & 15)) * QKV_STRIDE +
                               jp * 16 + ((lane >> 4) << 3)));
                uint32_t blo[2] = { rr[0], rr[1] };
                uint32_t bhi[2] = { rr[2], rr[3] };
                mma_f16(of[jp * 2], pa[kk], blo);
                mma_f16(of[jp * 2 + 1], pa[kk], bhi);
            }
        }
    }

    float inv0 = 1.f / l0, inv1 = 1.f / l1;
    int r = wid * 16 + (lane >> 2);
    int c0 = (lane & 3) * 2;
    #pragma unroll
    for (int j = 0; j < 8; j++) {
        int col = j * 8 + c0;
        *(__half2*)(O + base + (size_t)(q0 + r) * D_ + col) =
            __floats2half2_rn(of[j][0] * inv0, of[j][1] * inv0);
        *(__half2*)(O + base + (size_t)(q0 + r + 8) * D_ + col) =
            __floats2half2_rn(of[j][2] * inv1, of[j][3] * inv1);
    }
}

// ---------------------------------------------------------------------------
// Launch
// ---------------------------------------------------------------------------
extern "C" void kernel_launch(void* const* d_in, const int* in_sizes, int n_in,
                              void* d_out, int out_size)
{
    const float* x  = (const float*)d_in[0];
    const float* fr = (const float*)d_in[1];
    const float* wq = (const float*)d_in[2];
    const float* bq = (const float*)d_in[3];
    const float* wk = (const float*)d_in[4];
    const float* bk = (const float*)d_in[5];
    const float* wv = (const float*)d_in[6];
    const float* bv = (const float*)d_in[7];
    const float* wo = (const float*)d_in[8];
    const float* bo = (const float*)d_in[9];
    float* out = (float*)d_out;

    __half *xh, *wqh, *wkh, *wvh, *woh, *qh, *kh, *vh, *oh;
    cudaGetSymbolAddress((void**)&xh,  g_xh);
    cudaGetSymbolAddress((void**)&wqh, g_wqh);
    cudaGetSymbolAddress((void**)&wkh, g_wkh);
    cudaGetSymbolAddress((void**)&wvh, g_wvh);
    cudaGetSymbolAddress((void**)&woh, g_woh);
    cudaGetSymbolAddress((void**)&qh,  g_qh);
    cudaGetSymbolAddress((void**)&kh,  g_kh);
    cudaGetSymbolAddress((void**)&vh,  g_vh);
    cudaGetSymbolAddress((void**)&oh,  g_oh);

    cudaFuncSetAttribute(gemm_cp<true, __half>,
                         cudaFuncAttributeMaxDynamicSharedMemorySize, GEMM_SMEM);
    cudaFuncSetAttribute(gemm_cp<false, __half>,
                         cudaFuncAttributeMaxDynamicSharedMemorySize, GEMM_SMEM);
    cudaFuncSetAttribute(gemm_cp<false, float>,
                         cudaFuncAttributeMaxDynamicSharedMemorySize, GEMM_SMEM);
    cudaFuncSetAttribute(attn_mma,
                         cudaFuncAttributeMaxDynamicSharedMemorySize, ATTN_SMEM);

    const int NX = B_ * S_ * D_, NW = D_ * D_;
    f2h<<<NX / 1024, 256>>>(x, xh, NX);
    f2h<<<NW / 1024, 256>>>(wq, wqh, NW);
    f2h<<<NW / 1024, 256>>>(wk, wkh, NW);
    f2h<<<NW / 1024, 256>>>(wv, wvh, NW);
    f2h<<<NW / 1024, 256>>>(wo, woh, NW);

    dim3 gg(D_ / 128, (B_ * S_) / 128);  // (8, 32)
    gemm_cp<true,  __half><<<gg, 256, GEMM_SMEM>>>(xh, wqh, bq, fr, qh, B_*S_, D_, D_);
    gemm_cp<true,  __half><<<gg, 256, GEMM_SMEM>>>(xh, wkh, bk, fr, kh, B_*S_, D_, D_);
    gemm_cp<false, __half><<<gg, 256, GEMM_SMEM>>>(xh, wvh, bv, fr, vh, B_*S_, D_, D_);

    attn_mma<<<dim3(S_ / 128, H_, B_), 256, ATTN_SMEM>>>(qh, kh, vh, oh);

    gemm_cp<false, float><<<gg, 256, GEMM_SMEM>>>(oh, woh, bo, fr, out, B_*S_, D_, D_);
}

// round 8
// speedup vs baseline: 6.3447x; 1.0404x over previous
#include <cuda_runtime.h>
#include <cuda_fp16.h>
#include <math.h>
#include <stdint.h>

#define B_ 2
#define S_ 2048
#define D_ 1024
#define H_ 16
#define HD_ 64
#define LOG2E 1.4426950408889634f

// fp16 scratch (static device globals: allocation-free)
__device__ __half g_xh[B_*S_*D_];
__device__ __half g_wqh[D_*D_];
__device__ __half g_wkh[D_*D_];
__device__ __half g_wvh[D_*D_];
__device__ __half g_woh[D_*D_];
__device__ __half g_qh[B_*S_*D_];
__device__ __half g_kh[B_*S_*D_];
__device__ __half g_vh[B_*S_*D_];
__device__ __half g_oh[B_*S_*D_];

// ---------------------------------------------------------------------------
// helpers
// ---------------------------------------------------------------------------
__device__ __forceinline__ uint32_t s2u(const void* p) {
    return (uint32_t)__cvta_generic_to_shared(p);
}
__device__ __forceinline__ void ldsm4(uint32_t r[4], uint32_t a) {
    asm volatile("ldmatrix.sync.aligned.m8n8.x4.shared.b16 {%0,%1,%2,%3},[%4];\n"
        : "=r"(r[0]), "=r"(r[1]), "=r"(r[2]), "=r"(r[3]) : "r"(a));
}
__device__ __forceinline__ void ldsm4t(uint32_t r[4], uint32_t a) {
    asm volatile("ldmatrix.sync.aligned.m8n8.x4.trans.shared.b16 {%0,%1,%2,%3},[%4];\n"
        : "=r"(r[0]), "=r"(r[1]), "=r"(r[2]), "=r"(r[3]) : "r"(a));
}
__device__ __forceinline__ void mma_f16(float c[4], const uint32_t a[4], const uint32_t b[2]) {
    asm volatile(
        "mma.sync.aligned.m16n8k16.row.col.f32.f16.f16.f32 "
        "{%0,%1,%2,%3},{%4,%5,%6,%7},{%8,%9},{%0,%1,%2,%3};\n"
        : "+f"(c[0]), "+f"(c[1]), "+f"(c[2]), "+f"(c[3])
        : "r"(a[0]), "r"(a[1]), "r"(a[2]), "r"(a[3]), "r"(b[0]), "r"(b[1]));
}
__device__ __forceinline__ uint32_t pack_h2(float a, float b) {
    __half2 h = __floats2half2_rn(a, b);
    return *reinterpret_cast<uint32_t*>(&h);
}
// fp32 MUFU exp2 (rare path: rescale alpha)
__device__ __forceinline__ float ex2f(float x) {
    float y;
    asm("ex2.approx.ftz.f32 %0,%1;" : "=f"(y) : "f"(x));
    return y;
}
// half2 MUFU exp2: 2 elements per MUFU op, result directly packed
__device__ __forceinline__ uint32_t h2exp2(uint32_t a) {
    uint32_t d;
    asm("ex2.approx.f16x2 %0,%1;" : "=r"(d) : "r"(a));
    return d;
}
#define CP16(dst, src) \
    asm volatile("cp.async.ca.shared.global [%0], [%1], 16;\n" :: "r"(dst), "l"(src))
#define CP_COMMIT() asm volatile("cp.async.commit_group;\n" ::: "memory")
#define CP_WAIT(n)  asm volatile("cp.async.wait_group " #n ";\n" ::: "memory")

// ---------------------------------------------------------------------------
// Fused fp32 -> fp16 convert for x + 4 weight matrices
// ---------------------------------------------------------------------------
__global__ void conv_all(
    const float* __restrict__ x,
    const float* __restrict__ wq, const float* __restrict__ wk,
    const float* __restrict__ wv, const float* __restrict__ wo,
    __half* __restrict__ xh,
    __half* __restrict__ wqh, __half* __restrict__ wkh,
    __half* __restrict__ wvh, __half* __restrict__ woh)
{
    const int NX = B_ * S_ * D_;           // 4M
    int i4 = (blockIdx.x * blockDim.x + threadIdx.x) * 4;
    const float* s; __half* d; int off;
    if (i4 < NX) { s = x; d = xh; off = i4; }
    else {
        int r = i4 - NX;
        int w = r >> 20;                   // D_*D_ = 1M = 2^20
        off = r & ((1 << 20) - 1);
        s = (w == 0) ? wq : (w == 1) ? wk : (w == 2) ? wv : wo;
        d = (w == 0) ? wqh : (w == 1) ? wkh : (w == 2) ? wvh : woh;
    }
    float4 v = *(const float4*)(s + off);
    *(__half2*)(d + off)     = __floats2half2_rn(v.x, v.y);
    *(__half2*)(d + off + 2) = __floats2half2_rn(v.z, v.w);
}

// ---------------------------------------------------------------------------
// GEMM body: C[M,N] = A[M,K] @ W[K,N] + bias, fp16 HMMA fp32-accum,
// block 128x128, BK=32, 4-stage cp.async, optional fused RoPE.
// ---------------------------------------------------------------------------
#define BK 32
#define AS_STRIDE 40
#define BS_STRIDE 136
#define A_ST_SZ (128 * AS_STRIDE)
#define B_ST_SZ (BK * BS_STRIDE)
#define GEMM_SMEM ((4 * (A_ST_SZ + B_ST_SZ)) * 2)

template<typename OT>
__device__ __forceinline__ void gemm_body(
    const __half* __restrict__ A, const __half* __restrict__ W,
    const float* __restrict__ bias, const float* __restrict__ freqs,
    OT* __restrict__ C, int M, int N, int K, bool rope, __half* sm)
{
    __half* As = sm;
    __half* Bs = sm + 4 * A_ST_SZ;

    int tid = threadIdx.x, lane = tid & 31, wid = tid >> 5;
    int wm = wid & 1, wn = wid >> 1;
    int bm = blockIdx.y * 128, bn = blockIdx.x * 128;

    float acc[4][4][4];
    #pragma unroll
    for (int i = 0; i < 4; i++)
        #pragma unroll
        for (int j = 0; j < 4; j++)
            #pragma unroll
            for (int c = 0; c < 4; c++) acc[i][j][c] = 0.f;

    int ac0 = tid * 2;
    int a_r0 = ac0 >> 2, a_o0 = (ac0 & 3) * 8;
    int a_r1 = (ac0 + 1) >> 2, a_o1 = ((ac0 + 1) & 3) * 8;
    int bc0 = tid * 2;
    int b_r0 = bc0 >> 4, b_o0 = (bc0 & 15) * 8;
    int b_r1 = (bc0 + 1) >> 4, b_o1 = ((bc0 + 1) & 15) * 8;

    auto load_stage = [&](int s, int buf) {
        int k0 = s * BK;
        __half* ab = As + buf * A_ST_SZ;
        __half* bb = Bs + buf * B_ST_SZ;
        CP16(s2u(ab + a_r0 * AS_STRIDE + a_o0),
             A + (size_t)(bm + a_r0) * K + k0 + a_o0);
        CP16(s2u(ab + a_r1 * AS_STRIDE + a_o1),
             A + (size_t)(bm + a_r1) * K + k0 + a_o1);
        CP16(s2u(bb + b_r0 * BS_STRIDE + b_o0),
             W + (size_t)(k0 + b_r0) * N + bn + b_o0);
        CP16(s2u(bb + b_r1 * BS_STRIDE + b_o1),
             W + (size_t)(k0 + b_r1) * N + bn + b_o1);
    };

    int a_row = wm * 64 + (lane & 15);
    int a_colh = (lane >> 4) << 3;
    int b_krow = lane & 15;
    int b_coln = (lane >> 4) << 3;

    auto compute = [&](int buf) {
        const __half* ab = As + buf * A_ST_SZ;
        const __half* bb = Bs + buf * B_ST_SZ;
        #pragma unroll
        for (int kk = 0; kk < BK; kk += 16) {
            uint32_t af[4][4], bf[4][2];
            #pragma unroll
            for (int i = 0; i < 4; i++)
                ldsm4(af[i], s2u(ab + (a_row + i * 16) * AS_STRIDE + kk + a_colh));
            #pragma unroll
            for (int jp = 0; jp < 2; jp++) {
                uint32_t r[4];
                ldsm4t(r, s2u(bb + (kk + b_krow) * BS_STRIDE + wn * 32 + jp * 16 + b_coln));
                bf[jp * 2][0] = r[0]; bf[jp * 2][1] = r[1];
                bf[jp * 2 + 1][0] = r[2]; bf[jp * 2 + 1][1] = r[3];
            }
            #pragma unroll
            for (int i = 0; i < 4; i++)
                #pragma unroll
                for (int j = 0; j < 4; j++)
                    mma_f16(acc[i][j], af[i], bf[j]);
        }
    };

    const int NS = K / BK;   // 32
    load_stage(0, 0); CP_COMMIT();
    load_stage(1, 1); CP_COMMIT();
    load_stage(2, 2); CP_COMMIT();

    for (int s = 0; s < NS; s++) {
        CP_WAIT(2);
        __syncthreads();
        compute(s & 3);
        if (s + 3 < NS) load_stage(s + 3, (s + 3) & 3);
        CP_COMMIT();
    }

    int r0 = bm + wm * 64 + (lane >> 2);
    int c00 = bn + wn * 32 + (lane & 3) * 2;
    #pragma unroll
    for (int i = 0; i < 4; i++) {
        int row = r0 + i * 16;
        #pragma unroll
        for (int j = 0; j < 4; j++) {
            int col = c00 + j * 8;
            float2 bv = *(const float2*)&bias[col];
            float v0 = acc[i][j][0] + bv.x, v1 = acc[i][j][1] + bv.y;
            float v2 = acc[i][j][2] + bv.x, v3 = acc[i][j][3] + bv.y;
            if (rope) {
                int hp = col & 63;
                float2 c1 = *(const float2*)&freqs[(row & (S_ - 1)) * 64 + hp];
                float2 c2 = *(const float2*)&freqs[((row + 8) & (S_ - 1)) * 64 + hp];
                float t0 = v0 * c1.x - v1 * c1.y;
                float t1 = v0 * c1.y + v1 * c1.x;
                float t2 = v2 * c2.x - v3 * c2.y;
                float t3 = v2 * c2.y + v3 * c2.x;
                v0 = t0; v1 = t1; v2 = t2; v3 = t3;
            }
            if (sizeof(OT) == 4) {
                *(float2*)((float*)C + (size_t)row * N + col)       = make_float2(v0, v1);
                *(float2*)((float*)C + (size_t)(row + 8) * N + col) = make_float2(v2, v3);
            } else {
                *(__half2*)((__half*)C + (size_t)row * N + col)       = __floats2half2_rn(v0, v1);
                *(__half2*)((__half*)C + (size_t)(row + 8) * N + col) = __floats2half2_rn(v2, v3);
            }
        }
    }
}

// Fused QKV projection: blockIdx.z selects {W,bias,C}; rope for z<2.
__global__ __launch_bounds__(256) void gemm_qkv(
    const __half* __restrict__ A,
    const __half* __restrict__ w0, const __half* __restrict__ w1,
    const __half* __restrict__ w2,
    const float* __restrict__ b0, const float* __restrict__ b1,
    const float* __restrict__ b2,
    const float* __restrict__ freqs,
    __half* __restrict__ c0, __half* __restrict__ c1, __half* __restrict__ c2)
{
    extern __shared__ __half smq[];
    int z = blockIdx.z;
    const __half* W = (z == 0) ? w0 : (z == 1) ? w1 : w2;
    const float* bb = (z == 0) ? b0 : (z == 1) ? b1 : b2;
    __half* C = (z == 0) ? c0 : (z == 1) ? c1 : c2;
    gemm_body<__half>(A, W, bb, freqs, C, B_ * S_, D_, D_, z < 2, smq);
}

// Output projection
__global__ __launch_bounds__(256) void gemm_o(
    const __half* __restrict__ A, const __half* __restrict__ W,
    const float* __restrict__ bias, float* __restrict__ C)
{
    extern __shared__ __half smo[];
    gemm_body<float>(A, W, bias, (const float*)nullptr, C, B_ * S_, D_, D_, false, smo);
}

// ---------------------------------------------------------------------------
// Flash attention, fp16 HMMA. CTA: 128 queries of one (b,h); 8 warps x 16q.
// cp.async double-buffered K/V; half2 MUFU exp; row-sums via ones-MMA.
// ---------------------------------------------------------------------------
#define QKV_STRIDE 72
#define Q_SZ (128 * QKV_STRIDE)
#define KV_SZ (64 * QKV_STRIDE)
#define ATTN_SMEM ((Q_SZ + 4 * KV_SZ) * 2)

__global__ __launch_bounds__(256) void attn_mma(
    const __half* __restrict__ Q, const __half* __restrict__ K,
    const __half* __restrict__ V, __half* __restrict__ O)
{
    extern __shared__ __half asm_[];
    __half* Qs = asm_;
    __half* Ks = asm_ + Q_SZ;
    __half* Vs = asm_ + Q_SZ + 2 * KV_SZ;

    int tid = threadIdx.x, lane = tid & 31, wid = tid >> 5;
    int q0 = blockIdx.x * 128, h = blockIdx.y, b = blockIdx.z;
    const size_t base = (size_t)b * S_ * D_ + h * HD_;

    #pragma unroll
    for (int p = 0; p < 4; p++) {
        int c = tid + p * 256;
        int row = c >> 3, off = (c & 7) * 8;
        CP16(s2u(Qs + row * QKV_STRIDE + off),
             Q + base + (size_t)(q0 + row) * D_ + off);
    }
    CP_COMMIT();

    auto load_kv = [&](int t, int buf) {
        __half* kb = Ks + buf * KV_SZ;
        __half* vb = Vs + buf * KV_SZ;
        #pragma unroll
        for (int p = 0; p < 4; p++) {
            int c = tid + p * 256;
            int row = (c >> 3) & 63, off = (c & 7) * 8;
            if (c < 512)
                CP16(s2u(kb + row * QKV_STRIDE + off),
                     K + base + (size_t)(t * 64 + row) * D_ + off);
            else
                CP16(s2u(vb + row * QKV_STRIDE + off),
                     V + base + (size_t)(t * 64 + row) * D_ + off);
        }
    };
    load_kv(0, 0); CP_COMMIT();

    CP_WAIT(1);
    __syncthreads();

    uint32_t aq[4][4];
    {
        int r = wid * 16 + (lane & 15);
        int ch = (lane >> 4) << 3;
        #pragma unroll
        for (int kt = 0; kt < 4; kt++)
            ldsm4(aq[kt], s2u(Qs + r * QKV_STRIDE + kt * 16 + ch));
    }

    float of[8][4];
    #pragma unroll
    for (int j = 0; j < 8; j++)
        #pragma unroll
        for (int c = 0; c < 4; c++) of[j][c] = 0.f;
    float m0 = -1e30f, m1 = -1e30f, l0 = 0.f, l1 = 0.f;
    const float cs_ = 0.125f * LOG2E;
    const uint32_t ones2 = 0x3C003C00u;
    const uint32_t ob[2] = { ones2, ones2 };

    for (int t = 0; t < S_ / 64; t++) {
        CP_WAIT(0);
        __syncthreads();
        if (t + 1 < S_ / 64) load_kv(t + 1, (t + 1) & 1);
        CP_COMMIT();

        const __half* kb = Ks + (t & 1) * KV_SZ;
        const __half* vb = Vs + (t & 1) * KV_SZ;

        // S = Q @ K^T (raw scores)
        float sf[8][4];
        #pragma unroll
        for (int j = 0; j < 8; j++)
            #pragma unroll
            for (int c = 0; c < 4; c++) sf[j][c] = 0.f;

        #pragma unroll
        for (int kt = 0; kt < 4; kt++) {
            #pragma unroll
            for (int jp = 0; jp < 4; jp++) {
                uint32_t rr[4];
                ldsm4(rr, s2u(kb + (jp * 16 + (lane & 15)) * QKV_STRIDE +
                              kt * 16 + ((lane >> 4) << 3)));
                uint32_t blo[2] = { rr[0], rr[2] };
                uint32_t bhi[2] = { rr[1], rr[3] };
                mma_f16(sf[jp * 2], aq[kt], blo);
                mma_f16(sf[jp * 2 + 1], aq[kt], bhi);
            }
        }

        // tile maxima (quad reduce)
        float mx0 = -1e30f, mx1 = -1e30f;
        #pragma unroll
        for (int j = 0; j < 8; j++) {
            mx0 = fmaxf(mx0, fmaxf(sf[j][0], sf[j][1]));
            mx1 = fmaxf(mx1, fmaxf(sf[j][2], sf[j][3]));
        }
        mx0 = fmaxf(mx0, __shfl_xor_sync(0xffffffffu, mx0, 1, 4));
        mx0 = fmaxf(mx0, __shfl_xor_sync(0xffffffffu, mx0, 2, 4));
        mx1 = fmaxf(mx1, __shfl_xor_sync(0xffffffffu, mx1, 1, 4));
        mx1 = fmaxf(mx1, __shfl_xor_sync(0xffffffffu, mx1, 2, 4));

        if (mx0 > m0) {
            float alpha = ex2f((m0 - mx0) * cs_);
            m0 = mx0; l0 *= alpha;
            #pragma unroll
            for (int j = 0; j < 8; j++) { of[j][0] *= alpha; of[j][1] *= alpha; }
        }
        if (mx1 > m1) {
            float alpha = ex2f((m1 - mx1) * cs_);
            m1 = mx1; l1 *= alpha;
            #pragma unroll
            for (int j = 0; j < 8; j++) { of[j][2] *= alpha; of[j][3] *= alpha; }
        }

        // P = exp2(s*cs - m*cs): fp32 args, packed, half2 MUFU -> P A-frags
        float nm0 = -m0 * cs_, nm1 = -m1 * cs_;
        uint32_t pa[4][4];
        #pragma unroll
        for (int kk = 0; kk < 4; kk++) {
            int ja = 2 * kk, jb = 2 * kk + 1;
            pa[kk][0] = h2exp2(pack_h2(fmaf(sf[ja][0], cs_, nm0),
                                       fmaf(sf[ja][1], cs_, nm0)));
            pa[kk][1] = h2exp2(pack_h2(fmaf(sf[ja][2], cs_, nm1),
                                       fmaf(sf[ja][3], cs_, nm1)));
            pa[kk][2] = h2exp2(pack_h2(fmaf(sf[jb][0], cs_, nm0),
                                       fmaf(sf[jb][1], cs_, nm0)));
            pa[kk][3] = h2exp2(pack_h2(fmaf(sf[jb][2], cs_, nm1),
                                       fmaf(sf[jb][3], cs_, nm1)));
        }

        // row sums l += P @ ones (tensor core, matches fp16 P exactly)
        float lacc[4] = { 0.f, 0.f, 0.f, 0.f };
        #pragma unroll
        for (int kk = 0; kk < 4; kk++)
            mma_f16(lacc, pa[kk], ob);
        l0 += lacc[0];
        l1 += lacc[2];

        // O += P @ V
        #pragma unroll
        for (int kk = 0; kk < 4; kk++) {
            #pragma unroll
            for (int jp = 0; jp < 4; jp++) {
                uint32_t rr[4];
                ldsm4t(rr, s2u(vb + (kk * 16 + (lane & 15)) * QKV_STRIDE +
                               jp * 16 + ((lane >> 4) << 3)));
                uint32_t blo[2] = { rr[0], rr[1] };
                uint32_t bhi[2] = { rr[2], rr[3] };
                mma_f16(of[jp * 2], pa[kk], blo);
                mma_f16(of[jp * 2 + 1], pa[kk], bhi);
            }
        }
    }

    float inv0 = 1.f / l0, inv1 = 1.f / l1;
    int r = wid * 16 + (lane >> 2);
    int c0 = (lane & 3) * 2;
    #pragma unroll
    for (int j = 0; j < 8; j++) {
        int col = j * 8 + c0;
        *(__half2*)(O + base + (size_t)(q0 + r) * D_ + col) =
            __floats2half2_rn(of[j][0] * inv0, of[j][1] * inv0);
        *(__half2*)(O + base + (size_t)(q0 + r + 8) * D_ + col) =
            __floats2half2_rn(of[j][2] * inv1, of[j][3] * inv1);
    }
}

// ---------------------------------------------------------------------------
// Launch
// ---------------------------------------------------------------------------
extern "C" void kernel_launch(void* const* d_in, const int* in_sizes, int n_in,
                              void* d_out, int out_size)
{
    const float* x  = (const float*)d_in[0];
    const float* fr = (const float*)d_in[1];
    const float* wq = (const float*)d_in[2];
    const float* bq = (const float*)d_in[3];
    const float* wk = (const float*)d_in[4];
    const float* bk = (const float*)d_in[5];
    const float* wv = (const float*)d_in[6];
    const float* bv = (const float*)d_in[7];
    const float* wo = (const float*)d_in[8];
    const float* bo = (const float*)d_in[9];
    float* out = (float*)d_out;

    __half *xh, *wqh, *wkh, *wvh, *woh, *qh, *kh, *vh, *oh;
    cudaGetSymbolAddress((void**)&xh,  g_xh);
    cudaGetSymbolAddress((void**)&wqh, g_wqh);
    cudaGetSymbolAddress((void**)&wkh, g_wkh);
    cudaGetSymbolAddress((void**)&wvh, g_wvh);
    cudaGetSymbolAddress((void**)&woh, g_woh);
    cudaGetSymbolAddress((void**)&qh,  g_qh);
    cudaGetSymbolAddress((void**)&kh,  g_kh);
    cudaGetSymbolAddress((void**)&vh,  g_vh);
    cudaGetSymbolAddress((void**)&oh,  g_oh);

    cudaFuncSetAttribute(gemm_qkv,
                         cudaFuncAttributeMaxDynamicSharedMemorySize, GEMM_SMEM);
    cudaFuncSetAttribute(gemm_o,
                         cudaFuncAttributeMaxDynamicSharedMemorySize, GEMM_SMEM);
    cudaFuncSetAttribute(attn_mma,
                         cudaFuncAttributeMaxDynamicSharedMemorySize, ATTN_SMEM);

    const int NTOT = B_ * S_ * D_ + 4 * D_ * D_;   // 8M elements
    conv_all<<<NTOT / 1024, 256>>>(x, wq, wk, wv, wo, xh, wqh, wkh, wvh, woh);

    dim3 gq(D_ / 128, (B_ * S_) / 128, 3);   // (8, 32, 3)
    gemm_qkv<<<gq, 256, GEMM_SMEM>>>(xh, wqh, wkh, wvh, bq, bk, bv, fr, qh, kh, vh);

    attn_mma<<<dim3(S_ / 128, H_, B_), 256, ATTN_SMEM>>>(qh, kh, vh, oh);

    dim3 gg(D_ / 128, (B_ * S_) / 128);      // (8, 32)
    gemm_o<<<gg, 256, GEMM_SMEM>>>(oh, woh, bo, out);
}

// round 9
// speedup vs baseline: 7.0068x; 1.1043x over previous
#include <cuda_runtime.h>
#include <cuda_fp16.h>
#include <math.h>
#include <stdint.h>

#define B_ 2
#define S_ 2048
#define D_ 1024
#define H_ 16
#define HD_ 64
#define LOG2E 1.4426950408889634f

// fp16 scratch (static device globals: allocation-free)
__device__ __half g_xh[B_*S_*D_];
__device__ __half g_wqh[D_*D_];
__device__ __half g_wkh[D_*D_];
__device__ __half g_wvh[D_*D_];
__device__ __half g_woh[D_*D_];
__device__ __half g_qh[B_*S_*D_];
__device__ __half g_kh[B_*S_*D_];
__device__ __half g_vh[B_*S_*D_];
__device__ __half g_oh[B_*S_*D_];

// ---------------------------------------------------------------------------
// helpers
// ---------------------------------------------------------------------------
__device__ __forceinline__ uint32_t s2u(const void* p) {
    return (uint32_t)__cvta_generic_to_shared(p);
}
__device__ __forceinline__ void ldsm4(uint32_t r[4], uint32_t a) {
    asm volatile("ldmatrix.sync.aligned.m8n8.x4.shared.b16 {%0,%1,%2,%3},[%4];\n"
        : "=r"(r[0]), "=r"(r[1]), "=r"(r[2]), "=r"(r[3]) : "r"(a));
}
__device__ __forceinline__ void ldsm4t(uint32_t r[4], uint32_t a) {
    asm volatile("ldmatrix.sync.aligned.m8n8.x4.trans.shared.b16 {%0,%1,%2,%3},[%4];\n"
        : "=r"(r[0]), "=r"(r[1]), "=r"(r[2]), "=r"(r[3]) : "r"(a));
}
__device__ __forceinline__ void mma_f16(float c[4], const uint32_t a[4], const uint32_t b[2]) {
    asm volatile(
        "mma.sync.aligned.m16n8k16.row.col.f32.f16.f16.f32 "
        "{%0,%1,%2,%3},{%4,%5,%6,%7},{%8,%9},{%0,%1,%2,%3};\n"
        : "+f"(c[0]), "+f"(c[1]), "+f"(c[2]), "+f"(c[3])
        : "r"(a[0]), "r"(a[1]), "r"(a[2]), "r"(a[3]), "r"(b[0]), "r"(b[1]));
}
__device__ __forceinline__ uint32_t pack_h2(float a, float b) {
    __half2 h = __floats2half2_rn(a, b);
    return *reinterpret_cast<uint32_t*>(&h);
}
// fp32 MUFU exp2 (rare path: rescale alpha)
__device__ __forceinline__ float ex2f(float x) {
    float y;
    asm("ex2.approx.ftz.f32 %0,%1;" : "=f"(y) : "f"(x));
    return y;
}
// half2 MUFU exp2: 2 elements per MUFU op, result directly packed
__device__ __forceinline__ uint32_t h2exp2(uint32_t a) {
    uint32_t d;
    asm("ex2.approx.f16x2 %0,%1;" : "=r"(d) : "r"(a));
    return d;
}
#define CP16(dst, src) \
    asm volatile("cp.async.ca.shared.global [%0], [%1], 16;\n" :: "r"(dst), "l"(src))
#define CP_COMMIT() asm volatile("cp.async.commit_group;\n" ::: "memory")
#define CP_WAIT(n)  asm volatile("cp.async.wait_group " #n ";\n" ::: "memory")

// ---------------------------------------------------------------------------
// Fused fp32 -> fp16 convert for x + 4 weight matrices
// ---------------------------------------------------------------------------
__global__ void conv_all(
    const float* __restrict__ x,
    const float* __restrict__ wq, const float* __restrict__ wk,
    const float* __restrict__ wv, const float* __restrict__ wo,
    __half* __restrict__ xh,
    __half* __restrict__ wqh, __half* __restrict__ wkh,
    __half* __restrict__ wvh, __half* __restrict__ woh)
{
    const int NX = B_ * S_ * D_;           // 4M
    int i4 = (blockIdx.x * blockDim.x + threadIdx.x) * 4;
    const float* s; __half* d; int off;
    if (i4 < NX) { s = x; d = xh; off = i4; }
    else {
        int r = i4 - NX;
        int w = r >> 20;                   // D_*D_ = 1M = 2^20
        off = r & ((1 << 20) - 1);
        s = (w == 0) ? wq : (w == 1) ? wk : (w == 2) ? wv : wo;
        d = (w == 0) ? wqh : (w == 1) ? wkh : (w == 2) ? wvh : woh;
    }
    float4 v = *(const float4*)(s + off);
    *(__half2*)(d + off)     = __floats2half2_rn(v.x, v.y);
    *(__half2*)(d + off + 2) = __floats2half2_rn(v.z, v.w);
}

// ---------------------------------------------------------------------------
// GEMM body: C[M,N] = A[M,K] @ W[K,N] + bias, fp16 HMMA fp32-accum.
// Block 128x128, 4 warps (2m x 2n), warp tile 64x64 (0.25 ldsm/MMA),
// BK=32, 4-stage cp.async, optional fused RoPE.
// ---------------------------------------------------------------------------
#define BK 32
#define AS_STRIDE 40
#define BS_STRIDE 136
#define A_ST_SZ (128 * AS_STRIDE)
#define B_ST_SZ (BK * BS_STRIDE)
#define GEMM_SMEM ((4 * (A_ST_SZ + B_ST_SZ)) * 2)

template<typename OT>
__device__ __forceinline__ void gemm_body(
    const __half* __restrict__ A, const __half* __restrict__ W,
    const float* __restrict__ bias, const float* __restrict__ freqs,
    OT* __restrict__ C, int M, int N, int K, bool rope, __half* sm)
{
    __half* As = sm;
    __half* Bs = sm + 4 * A_ST_SZ;

    int tid = threadIdx.x, lane = tid & 31, wid = tid >> 5;
    int wm = wid & 1, wn = wid >> 1;          // 2x2 warp grid
    int bm = blockIdx.y * 128, bn = blockIdx.x * 128;

    float acc[4][8][4];
    #pragma unroll
    for (int i = 0; i < 4; i++)
        #pragma unroll
        for (int j = 0; j < 8; j++)
            #pragma unroll
            for (int c = 0; c < 4; c++) acc[i][j][c] = 0.f;

    auto load_stage = [&](int s, int buf) {
        int k0 = s * BK;
        __half* ab = As + buf * A_ST_SZ;
        __half* bb = Bs + buf * B_ST_SZ;
        #pragma unroll
        for (int p = 0; p < 4; p++) {          // A: 512 chunks / 128 thr
            int c = tid + p * 128;
            int r = c >> 2, o = (c & 3) * 8;
            CP16(s2u(ab + r * AS_STRIDE + o),
                 A + (size_t)(bm + r) * K + k0 + o);
        }
        #pragma unroll
        for (int p = 0; p < 4; p++) {          // B: 512 chunks / 128 thr
            int c = tid + p * 128;
            int r = c >> 4, o = (c & 15) * 8;
            CP16(s2u(bb + r * BS_STRIDE + o),
                 W + (size_t)(k0 + r) * N + bn + o);
        }
    };

    int a_row = wm * 64 + (lane & 15);
    int a_colh = (lane >> 4) << 3;
    int b_krow = lane & 15;
    int b_coln = (lane >> 4) << 3;

    auto compute = [&](int buf) {
        const __half* ab = As + buf * A_ST_SZ;
        const __half* bb = Bs + buf * B_ST_SZ;
        #pragma unroll
        for (int kk = 0; kk < BK; kk += 16) {
            uint32_t af[4][4], bf[8][2];
            #pragma unroll
            for (int i = 0; i < 4; i++)
                ldsm4(af[i], s2u(ab + (a_row + i * 16) * AS_STRIDE + kk + a_colh));
            #pragma unroll
            for (int jp = 0; jp < 4; jp++) {
                uint32_t r[4];
                ldsm4t(r, s2u(bb + (kk + b_krow) * BS_STRIDE + wn * 64 + jp * 16 + b_coln));
                bf[jp * 2][0] = r[0]; bf[jp * 2][1] = r[1];
                bf[jp * 2 + 1][0] = r[2]; bf[jp * 2 + 1][1] = r[3];
            }
            #pragma unroll
            for (int i = 0; i < 4; i++)
                #pragma unroll
                for (int j = 0; j < 8; j++)
                    mma_f16(acc[i][j], af[i], bf[j]);
        }
    };

    const int NS = K / BK;   // 32
    load_stage(0, 0); CP_COMMIT();
    load_stage(1, 1); CP_COMMIT();
    load_stage(2, 2); CP_COMMIT();

    for (int s = 0; s < NS; s++) {
        CP_WAIT(2);
        __syncthreads();
        compute(s & 3);
        if (s + 3 < NS) load_stage(s + 3, (s + 3) & 3);
        CP_COMMIT();
    }

    int r0 = bm + wm * 64 + (lane >> 2);
    int c00 = bn + wn * 64 + (lane & 3) * 2;
    #pragma unroll
    for (int i = 0; i < 4; i++) {
        int row = r0 + i * 16;
        #pragma unroll
        for (int j = 0; j < 8; j++) {
            int col = c00 + j * 8;
            float2 bv = *(const float2*)&bias[col];
            float v0 = acc[i][j][0] + bv.x, v1 = acc[i][j][1] + bv.y;
            float v2 = acc[i][j][2] + bv.x, v3 = acc[i][j][3] + bv.y;
            if (rope) {
                int hp = col & 63;
                float2 c1 = *(const float2*)&freqs[(row & (S_ - 1)) * 64 + hp];
                float2 c2 = *(const float2*)&freqs[((row + 8) & (S_ - 1)) * 64 + hp];
                float t0 = v0 * c1.x - v1 * c1.y;
                float t1 = v0 * c1.y + v1 * c1.x;
                float t2 = v2 * c2.x - v3 * c2.y;
                float t3 = v2 * c2.y + v3 * c2.x;
                v0 = t0; v1 = t1; v2 = t2; v3 = t3;
            }
            if (sizeof(OT) == 4) {
                *(float2*)((float*)C + (size_t)row * N + col)       = make_float2(v0, v1);
                *(float2*)((float*)C + (size_t)(row + 8) * N + col) = make_float2(v2, v3);
            } else {
                *(__half2*)((__half*)C + (size_t)row * N + col)       = __floats2half2_rn(v0, v1);
                *(__half2*)((__half*)C + (size_t)(row + 8) * N + col) = __floats2half2_rn(v2, v3);
            }
        }
    }
}

// Fused QKV projection: blockIdx.z selects {W,bias,C}; rope for z<2.
__global__ __launch_bounds__(128) void gemm_qkv(
    const __half* __restrict__ A,
    const __half* __restrict__ w0, const __half* __restrict__ w1,
    const __half* __restrict__ w2,
    const float* __restrict__ b0, const float* __restrict__ b1,
    const float* __restrict__ b2,
    const float* __restrict__ freqs,
    __half* __restrict__ c0, __half* __restrict__ c1, __half* __restrict__ c2)
{
    extern __shared__ __half smq[];
    int z = blockIdx.z;
    const __half* W = (z == 0) ? w0 : (z == 1) ? w1 : w2;
    const float* bb = (z == 0) ? b0 : (z == 1) ? b1 : b2;
    __half* C = (z == 0) ? c0 : (z == 1) ? c1 : c2;
    gemm_body<__half>(A, W, bb, freqs, C, B_ * S_, D_, D_, z < 2, smq);
}

// Output projection
__global__ __launch_bounds__(128) void gemm_o(
    const __half* __restrict__ A, const __half* __restrict__ W,
    const float* __restrict__ bias, float* __restrict__ C)
{
    extern __shared__ __half smo[];
    gemm_body<float>(A, W, bias, (const float*)nullptr, C, B_ * S_, D_, D_, false, smo);
}

// ---------------------------------------------------------------------------
// Flash attention, fp16 HMMA (unchanged). 128q CTA, 8 warps.
// ---------------------------------------------------------------------------
#define QKV_STRIDE 72
#define Q_SZ (128 * QKV_STRIDE)
#define KV_SZ (64 * QKV_STRIDE)
#define ATTN_SMEM ((Q_SZ + 4 * KV_SZ) * 2)

__global__ __launch_bounds__(256) void attn_mma(
    const __half* __restrict__ Q, const __half* __restrict__ K,
    const __half* __restrict__ V, __half* __restrict__ O)
{
    extern __shared__ __half asm_[];
    __half* Qs = asm_;
    __half* Ks = asm_ + Q_SZ;
    __half* Vs = asm_ + Q_SZ + 2 * KV_SZ;

    int tid = threadIdx.x, lane = tid & 31, wid = tid >> 5;
    int q0 = blockIdx.x * 128, h = blockIdx.y, b = blockIdx.z;
    const size_t base = (size_t)b * S_ * D_ + h * HD_;

    #pragma unroll
    for (int p = 0; p < 4; p++) {
        int c = tid + p * 256;
        int row = c >> 3, off = (c & 7) * 8;
        CP16(s2u(Qs + row * QKV_STRIDE + off),
             Q + base + (size_t)(q0 + row) * D_ + off);
    }
    CP_COMMIT();

    auto load_kv = [&](int t, int buf) {
        __half* kb = Ks + buf * KV_SZ;
        __half* vb = Vs + buf * KV_SZ;
        #pragma unroll
        for (int p = 0; p < 4; p++) {
            int c = tid + p * 256;
            int row = (c >> 3) & 63, off = (c & 7) * 8;
            if (c < 512)
                CP16(s2u(kb + row * QKV_STRIDE + off),
                     K + base + (size_t)(t * 64 + row) * D_ + off);
            else
                CP16(s2u(vb + row * QKV_STRIDE + off),
                     V + base + (size_t)(t * 64 + row) * D_ + off);
        }
    };
    load_kv(0, 0); CP_COMMIT();

    CP_WAIT(1);
    __syncthreads();

    uint32_t aq[4][4];
    {
        int r = wid * 16 + (lane & 15);
        int ch = (lane >> 4) << 3;
        #pragma unroll
        for (int kt = 0; kt < 4; kt++)
            ldsm4(aq[kt], s2u(Qs + r * QKV_STRIDE + kt * 16 + ch));
    }

    float of[8][4];
    #pragma unroll
    for (int j = 0; j < 8; j++)
        #pragma unroll
        for (int c = 0; c < 4; c++) of[j][c] = 0.f;
    float m0 = -1e30f, m1 = -1e30f, l0 = 0.f, l1 = 0.f;
    const float cs_ = 0.125f * LOG2E;
    const uint32_t ones2 = 0x3C003C00u;
    const uint32_t ob[2] = { ones2, ones2 };

    for (int t = 0; t < S_ / 64; t++) {
        CP_WAIT(0);
        __syncthreads();
        if (t + 1 < S_ / 64) load_kv(t + 1, (t + 1) & 1);
        CP_COMMIT();

        const __half* kb = Ks + (t & 1) * KV_SZ;
        const __half* vb = Vs + (t & 1) * KV_SZ;

        // S = Q @ K^T (raw scores)
        float sf[8][4];
        #pragma unroll
        for (int j = 0; j < 8; j++)
            #pragma unroll
            for (int c = 0; c < 4; c++) sf[j][c] = 0.f;

        #pragma unroll
        for (int kt = 0; kt < 4; kt++) {
            #pragma unroll
            for (int jp = 0; jp < 4; jp++) {
                uint32_t rr[4];
                ldsm4(rr, s2u(kb + (jp * 16 + (lane & 15)) * QKV_STRIDE +
                              kt * 16 + ((lane >> 4) << 3)));
                uint32_t blo[2] = { rr[0], rr[2] };
                uint32_t bhi[2] = { rr[1], rr[3] };
                mma_f16(sf[jp * 2], aq[kt], blo);
                mma_f16(sf[jp * 2 + 1], aq[kt], bhi);
            }
        }

        // tile maxima (quad reduce)
        float mx0 = -1e30f, mx1 = -1e30f;
        #pragma unroll
        for (int j = 0; j < 8; j++) {
            mx0 = fmaxf(mx0, fmaxf(sf[j][0], sf[j][1]));
            mx1 = fmaxf(mx1, fmaxf(sf[j][2], sf[j][3]));
        }
        mx0 = fmaxf(mx0, __shfl_xor_sync(0xffffffffu, mx0, 1, 4));
        mx0 = fmaxf(mx0, __shfl_xor_sync(0xffffffffu, mx0, 2, 4));
        mx1 = fmaxf(mx1, __shfl_xor_sync(0xffffffffu, mx1, 1, 4));
        mx1 = fmaxf(mx1, __shfl_xor_sync(0xffffffffu, mx1, 2, 4));

        if (mx0 > m0) {
            float alpha = ex2f((m0 - mx0) * cs_);
            m0 = mx0; l0 *= alpha;
            #pragma unroll
            for (int j = 0; j < 8; j++) { of[j][0] *= alpha; of[j][1] *= alpha; }
        }
        if (mx1 > m1) {
            float alpha = ex2f((m1 - mx1) * cs_);
            m1 = mx1; l1 *= alpha;
            #pragma unroll
            for (int j = 0; j < 8; j++) { of[j][2] *= alpha; of[j][3] *= alpha; }
        }

        // P = exp2(s*cs - m*cs): fp32 args, packed, half2 MUFU -> P A-frags
        float nm0 = -m0 * cs_, nm1 = -m1 * cs_;
        uint32_t pa[4][4];
        #pragma unroll
        for (int kk = 0; kk < 4; kk++) {
            int ja = 2 * kk, jb = 2 * kk + 1;
            pa[kk][0] = h2exp2(pack_h2(fmaf(sf[ja][0], cs_, nm0),
                                       fmaf(sf[ja][1], cs_, nm0)));
            pa[kk][1] = h2exp2(pack_h2(fmaf(sf[ja][2], cs_, nm1),
                                       fmaf(sf[ja][3], cs_, nm1)));
            pa[kk][2] = h2exp2(pack_h2(fmaf(sf[jb][0], cs_, nm0),
                                       fmaf(sf[jb][1], cs_, nm0)));
            pa[kk][3] = h2exp2(pack_h2(fmaf(sf[jb][2], cs_, nm1),
                                       fmaf(sf[jb][3], cs_, nm1)));
        }

        // row sums l += P @ ones (tensor core, matches fp16 P exactly)
        float lacc[4] = { 0.f, 0.f, 0.f, 0.f };
        #pragma unroll
        for (int kk = 0; kk < 4; kk++)
            mma_f16(lacc, pa[kk], ob);
        l0 += lacc[0];
        l1 += lacc[2];

        // O += P @ V
        #pragma unroll
        for (int kk = 0; kk < 4; kk++) {
            #pragma unroll
            for (int jp = 0; jp < 4; jp++) {
                uint32_t rr[4];
                ldsm4t(rr, s2u(vb + (kk * 16 + (lane & 15)) * QKV_STRIDE +
                               jp * 16 + ((lane >> 4) << 3)));
                uint32_t blo[2] = { rr[0], rr[1] };
                uint32_t bhi[2] = { rr[2], rr[3] };
                mma_f16(of[jp * 2], pa[kk], blo);
                mma_f16(of[jp * 2 + 1], pa[kk], bhi);
            }
        }
    }

    float inv0 = 1.f / l0, inv1 = 1.f / l1;
    int r = wid * 16 + (lane >> 2);
    int c0 = (lane & 3) * 2;
    #pragma unroll
    for (int j = 0; j < 8; j++) {
        int col = j * 8 + c0;
        *(__half2*)(O + base + (size_t)(q0 + r) * D_ + col) =
            __floats2half2_rn(of[j][0] * inv0, of[j][1] * inv0);
        *(__half2*)(O + base + (size_t)(q0 + r + 8) * D_ + col) =
            __floats2half2_rn(of[j][2] * inv1, of[j][3] * inv1);
    }
}

// ---------------------------------------------------------------------------
// Launch
// ---------------------------------------------------------------------------
extern "C" void kernel_launch(void* const* d_in, const int* in_sizes, int n_in,
                              void* d_out, int out_size)
{
    const float* x  = (const float*)d_in[0];
    const float* fr = (const float*)d_in[1];
    const float* wq = (const float*)d_in[2];
    const float* bq = (const float*)d_in[3];
    const float* wk = (const float*)d_in[4];
    const float* bk = (const float*)d_in[5];
    const float* wv = (const float*)d_in[6];
    const float* bv = (const float*)d_in[7];
    const float* wo = (const float*)d_in[8];
    const float* bo = (const float*)d_in[9];
    float* out = (float*)d_out;

    __half *xh, *wqh, *wkh, *wvh, *woh, *qh, *kh, *vh, *oh;
    cudaGetSymbolAddress((void**)&xh,  g_xh);
    cudaGetSymbolAddress((void**)&wqh, g_wqh);
    cudaGetSymbolAddress((void**)&wkh, g_wkh);
    cudaGetSymbolAddress((void**)&wvh, g_wvh);
    cudaGetSymbolAddress((void**)&woh, g_woh);
    cudaGetSymbolAddress((void**)&qh,  g_qh);
    cudaGetSymbolAddress((void**)&kh,  g_kh);
    cudaGetSymbolAddress((void**)&vh,  g_vh);
    cudaGetSymbolAddress((void**)&oh,  g_oh);

    cudaFuncSetAttribute(gemm_qkv,
                         cudaFuncAttributeMaxDynamicSharedMemorySize, GEMM_SMEM);
    cudaFuncSetAttribute(gemm_o,
                         cudaFuncAttributeMaxDynamicSharedMemorySize, GEMM_SMEM);
    cudaFuncSetAttribute(attn_mma,
                         cudaFuncAttributeMaxDynamicSharedMemorySize, ATTN_SMEM);

    const int NTOT = B_ * S_ * D_ + 4 * D_ * D_;   // 8M elements
    conv_all<<<NTOT / 1024, 256>>>(x, wq, wk, wv, wo, xh, wqh, wkh, wvh, woh);

    dim3 gq(D_ / 128, (B_ * S_) / 128, 3);   // (8, 32, 3)
    gemm_qkv<<<gq, 128, GEMM_SMEM>>>(xh, wqh, wkh, wvh, bq, bk, bv, fr, qh, kh, vh);

    attn_mma<<<dim3(S_ / 128, H_, B_), 256, ATTN_SMEM>>>(qh, kh, vh, oh);

    dim3 gg(D_ / 128, (B_ * S_) / 128);      // (8, 32)
    gemm_o<<<gg, 128, GEMM_SMEM>>>(oh, woh, bo, out);
}

// round 10
// speedup vs baseline: 7.1689x; 1.0231x over previous
#include <cuda_runtime.h>
#include <cuda_fp16.h>
#include <math.h>
#include <stdint.h>

#define B_ 2
#define S_ 2048
#define D_ 1024
#define H_ 16
#define HD_ 64
#define LOG2E 1.4426950408889634f

// fp16 scratch (static device globals: allocation-free)
__device__ __half g_xh[B_*S_*D_];
__device__ __half g_wqh[D_*D_];
__device__ __half g_wkh[D_*D_];
__device__ __half g_wvh[D_*D_];
__device__ __half g_woh[D_*D_];
__device__ __half g_qh[B_*S_*D_];
__device__ __half g_kh[B_*S_*D_];
__device__ __half g_vh[B_*S_*D_];
__device__ __half g_oh[B_*S_*D_];

// ---------------------------------------------------------------------------
// helpers
// ---------------------------------------------------------------------------
__device__ __forceinline__ uint32_t s2u(const void* p) {
    return (uint32_t)__cvta_generic_to_shared(p);
}
__device__ __forceinline__ void ldsm4(uint32_t r[4], uint32_t a) {
    asm volatile("ldmatrix.sync.aligned.m8n8.x4.shared.b16 {%0,%1,%2,%3},[%4];\n"
        : "=r"(r[0]), "=r"(r[1]), "=r"(r[2]), "=r"(r[3]) : "r"(a));
}
__device__ __forceinline__ void ldsm4t(uint32_t r[4], uint32_t a) {
    asm volatile("ldmatrix.sync.aligned.m8n8.x4.trans.shared.b16 {%0,%1,%2,%3},[%4];\n"
        : "=r"(r[0]), "=r"(r[1]), "=r"(r[2]), "=r"(r[3]) : "r"(a));
}
__device__ __forceinline__ void mma_f16(float c[4], const uint32_t a[4], const uint32_t b[2]) {
    asm volatile(
        "mma.sync.aligned.m16n8k16.row.col.f32.f16.f16.f32 "
        "{%0,%1,%2,%3},{%4,%5,%6,%7},{%8,%9},{%0,%1,%2,%3};\n"
        : "+f"(c[0]), "+f"(c[1]), "+f"(c[2]), "+f"(c[3])
        : "r"(a[0]), "r"(a[1]), "r"(a[2]), "r"(a[3]), "r"(b[0]), "r"(b[1]));
}
__device__ __forceinline__ uint32_t pack_h2(float a, float b) {
    __half2 h = __floats2half2_rn(a, b);
    return *reinterpret_cast<uint32_t*>(&h);
}
// fp32 MUFU exp2 (rare path: rescale alpha)
__device__ __forceinline__ float ex2f(float x) {
    float y;
    asm("ex2.approx.ftz.f32 %0,%1;" : "=f"(y) : "f"(x));
    return y;
}
// half2 MUFU exp2: 2 elements per MUFU op, result directly packed
__device__ __forceinline__ uint32_t h2exp2(uint32_t a) {
    uint32_t d;
    asm("ex2.approx.f16x2 %0,%1;" : "=r"(d) : "r"(a));
    return d;
}
#define CP16(dst, src) \
    asm volatile("cp.async.ca.shared.global [%0], [%1], 16;\n" :: "r"(dst), "l"(src))
#define CP_COMMIT() asm volatile("cp.async.commit_group;\n" ::: "memory")
#define CP_WAIT(n)  asm volatile("cp.async.wait_group " #n ";\n" ::: "memory")

// ---------------------------------------------------------------------------
// Fused fp32 -> fp16 convert for x + 4 weight matrices
// ---------------------------------------------------------------------------
__global__ void conv_all(
    const float* __restrict__ x,
    const float* __restrict__ wq, const float* __restrict__ wk,
    const float* __restrict__ wv, const float* __restrict__ wo,
    __half* __restrict__ xh,
    __half* __restrict__ wqh, __half* __restrict__ wkh,
    __half* __restrict__ wvh, __half* __restrict__ woh)
{
    const int NX = B_ * S_ * D_;           // 4M
    int i4 = (blockIdx.x * blockDim.x + threadIdx.x) * 4;
    const float* s; __half* d; int off;
    if (i4 < NX) { s = x; d = xh; off = i4; }
    else {
        int r = i4 - NX;
        int w = r >> 20;                   // D_*D_ = 1M = 2^20
        off = r & ((1 << 20) - 1);
        s = (w == 0) ? wq : (w == 1) ? wk : (w == 2) ? wv : wo;
        d = (w == 0) ? wqh : (w == 1) ? wkh : (w == 2) ? wvh : woh;
    }
    float4 v = *(const float4*)(s + off);
    *(__half2*)(d + off)     = __floats2half2_rn(v.x, v.y);
    *(__half2*)(d + off + 2) = __floats2half2_rn(v.z, v.w);
}

// ---------------------------------------------------------------------------
// GEMM body: C[M,N] = A[M,K] @ W[K,N] + bias, fp16 HMMA fp32-accum.
// Block 128x128, 4 warps (2m x 2n), warp tile 64x64 (0.25 ldsm/MMA),
// BK=32, 4-stage cp.async, optional fused RoPE.
// ---------------------------------------------------------------------------
#define BK 32
#define AS_STRIDE 40
#define BS_STRIDE 136
#define A_ST_SZ (128 * AS_STRIDE)
#define B_ST_SZ (BK * BS_STRIDE)
#define GEMM_SMEM ((4 * (A_ST_SZ + B_ST_SZ)) * 2)

template<typename OT>
__device__ __forceinline__ void gemm_body(
    const __half* __restrict__ A, const __half* __restrict__ W,
    const float* __restrict__ bias, const float* __restrict__ freqs,
    OT* __restrict__ C, int M, int N, int K, bool rope, __half* sm)
{
    __half* As = sm;
    __half* Bs = sm + 4 * A_ST_SZ;

    int tid = threadIdx.x, lane = tid & 31, wid = tid >> 5;
    int wm = wid & 1, wn = wid >> 1;          // 2x2 warp grid
    int bm = blockIdx.y * 128, bn = blockIdx.x * 128;

    float acc[4][8][4];
    #pragma unroll
    for (int i = 0; i < 4; i++)
        #pragma unroll
        for (int j = 0; j < 8; j++)
            #pragma unroll
            for (int c = 0; c < 4; c++) acc[i][j][c] = 0.f;

    auto load_stage = [&](int s, int buf) {
        int k0 = s * BK;
        __half* ab = As + buf * A_ST_SZ;
        __half* bb = Bs + buf * B_ST_SZ;
        #pragma unroll
        for (int p = 0; p < 4; p++) {          // A: 512 chunks / 128 thr
            int c = tid + p * 128;
            int r = c >> 2, o = (c & 3) * 8;
            CP16(s2u(ab + r * AS_STRIDE + o),
                 A + (size_t)(bm + r) * K + k0 + o);
        }
        #pragma unroll
        for (int p = 0; p < 4; p++) {          // B: 512 chunks / 128 thr
            int c = tid + p * 128;
            int r = c >> 4, o = (c & 15) * 8;
            CP16(s2u(bb + r * BS_STRIDE + o),
                 W + (size_t)(k0 + r) * N + bn + o);
        }
    };

    int a_row = wm * 64 + (lane & 15);
    int a_colh = (lane >> 4) << 3;
    int b_krow = lane & 15;
    int b_coln = (lane >> 4) << 3;

    auto compute = [&](int buf) {
        const __half* ab = As + buf * A_ST_SZ;
        const __half* bb = Bs + buf * B_ST_SZ;
        #pragma unroll
        for (int kk = 0; kk < BK; kk += 16) {
            uint32_t af[4][4], bf[8][2];
            #pragma unroll
            for (int i = 0; i < 4; i++)
                ldsm4(af[i], s2u(ab + (a_row + i * 16) * AS_STRIDE + kk + a_colh));
            #pragma unroll
            for (int jp = 0; jp < 4; jp++) {
                uint32_t r[4];
                ldsm4t(r, s2u(bb + (kk + b_krow) * BS_STRIDE + wn * 64 + jp * 16 + b_coln));
                bf[jp * 2][0] = r[0]; bf[jp * 2][1] = r[1];
                bf[jp * 2 + 1][0] = r[2]; bf[jp * 2 + 1][1] = r[3];
            }
            #pragma unroll
            for (int i = 0; i < 4; i++)
                #pragma unroll
                for (int j = 0; j < 8; j++)
                    mma_f16(acc[i][j], af[i], bf[j]);
        }
    };

    const int NS = K / BK;   // 32
    load_stage(0, 0); CP_COMMIT();
    load_stage(1, 1); CP_COMMIT();
    load_stage(2, 2); CP_COMMIT();

    for (int s = 0; s < NS; s++) {
        CP_WAIT(2);
        __syncthreads();
        compute(s & 3);
        if (s + 3 < NS) load_stage(s + 3, (s + 3) & 3);
        CP_COMMIT();
    }

    int r0 = bm + wm * 64 + (lane >> 2);
    int c00 = bn + wn * 64 + (lane & 3) * 2;
    #pragma unroll
    for (int i = 0; i < 4; i++) {
        int row = r0 + i * 16;
        #pragma unroll
        for (int j = 0; j < 8; j++) {
            int col = c00 + j * 8;
            float2 bv = *(const float2*)&bias[col];
            float v0 = acc[i][j][0] + bv.x, v1 = acc[i][j][1] + bv.y;
            float v2 = acc[i][j][2] + bv.x, v3 = acc[i][j][3] + bv.y;
            if (rope) {
                int hp = col & 63;
                float2 c1 = *(const float2*)&freqs[(row & (S_ - 1)) * 64 + hp];
                float2 c2 = *(const float2*)&freqs[((row + 8) & (S_ - 1)) * 64 + hp];
                float t0 = v0 * c1.x - v1 * c1.y;
                float t1 = v0 * c1.y + v1 * c1.x;
                float t2 = v2 * c2.x - v3 * c2.y;
                float t3 = v2 * c2.y + v3 * c2.x;
                v0 = t0; v1 = t1; v2 = t2; v3 = t3;
            }
            if (sizeof(OT) == 4) {
                *(float2*)((float*)C + (size_t)row * N + col)       = make_float2(v0, v1);
                *(float2*)((float*)C + (size_t)(row + 8) * N + col) = make_float2(v2, v3);
            } else {
                *(__half2*)((__half*)C + (size_t)row * N + col)       = __floats2half2_rn(v0, v1);
                *(__half2*)((__half*)C + (size_t)(row + 8) * N + col) = __floats2half2_rn(v2, v3);
            }
        }
    }
}

// Fused QKV projection: blockIdx.z selects {W,bias,C}; rope for z<2.
__global__ __launch_bounds__(128) void gemm_qkv(
    const __half* __restrict__ A,
    const __half* __restrict__ w0, const __half* __restrict__ w1,
    const __half* __restrict__ w2,
    const float* __restrict__ b0, const float* __restrict__ b1,
    const float* __restrict__ b2,
    const float* __restrict__ freqs,
    __half* __restrict__ c0, __half* __restrict__ c1, __half* __restrict__ c2)
{
    extern __shared__ __half smq[];
    int z = blockIdx.z;
    const __half* W = (z == 0) ? w0 : (z == 1) ? w1 : w2;
    const float* bb = (z == 0) ? b0 : (z == 1) ? b1 : b2;
    __half* C = (z == 0) ? c0 : (z == 1) ? c1 : c2;
    gemm_body<__half>(A, W, bb, freqs, C, B_ * S_, D_, D_, z < 2, smq);
}

// Output projection
__global__ __launch_bounds__(128) void gemm_o(
    const __half* __restrict__ A, const __half* __restrict__ W,
    const float* __restrict__ bias, float* __restrict__ C)
{
    extern __shared__ __half smo[];
    gemm_body<float>(A, W, bias, (const float*)nullptr, C, B_ * S_, D_, D_, false, smo);
}

// ---------------------------------------------------------------------------
// Flash attention, fp16 HMMA. CTA: 128 queries; 4 warps x 32q (2 groups of 16).
// K/V frags shared across both query groups: 0.24 ldsm/MMA.
// ---------------------------------------------------------------------------
#define QKV_STRIDE 72
#define Q_SZ (128 * QKV_STRIDE)
#define KV_SZ (64 * QKV_STRIDE)
#define ATTN_SMEM ((Q_SZ + 4 * KV_SZ) * 2)

__global__ __launch_bounds__(128) void attn_mma(
    const __half* __restrict__ Q, const __half* __restrict__ K,
    const __half* __restrict__ V, __half* __restrict__ O)
{
    extern __shared__ __half asm_[];
    __half* Qs = asm_;
    __half* Ks = asm_ + Q_SZ;
    __half* Vs = asm_ + Q_SZ + 2 * KV_SZ;

    int tid = threadIdx.x, lane = tid & 31, wid = tid >> 5;
    int q0 = blockIdx.x * 128, h = blockIdx.y, b = blockIdx.z;
    const size_t base = (size_t)b * S_ * D_ + h * HD_;

    // Q: 128 rows x 8 chunks = 1024 chunks, 8/thread (128 threads)
    #pragma unroll
    for (int p = 0; p < 8; p++) {
        int c = tid + p * 128;
        int row = c >> 3, off = (c & 7) * 8;
        CP16(s2u(Qs + row * QKV_STRIDE + off),
             Q + base + (size_t)(q0 + row) * D_ + off);
    }
    CP_COMMIT();

    auto load_kv = [&](int t, int buf) {
        __half* kb = Ks + buf * KV_SZ;
        __half* vb = Vs + buf * KV_SZ;
        #pragma unroll
        for (int p = 0; p < 8; p++) {
            int c = tid + p * 128;          // 0..1023; K first 512, V next
            int row = (c >> 3) & 63, off = (c & 7) * 8;
            if (c < 512)
                CP16(s2u(kb + row * QKV_STRIDE + off),
                     K + base + (size_t)(t * 64 + row) * D_ + off);
            else
                CP16(s2u(vb + row * QKV_STRIDE + off),
                     V + base + (size_t)(t * 64 + row) * D_ + off);
        }
    };
    load_kv(0, 0); CP_COMMIT();

    CP_WAIT(1);
    __syncthreads();

    // Q A-frags for both 16-row groups
    uint32_t aq[2][4][4];
    {
        int ch = (lane >> 4) << 3;
        #pragma unroll
        for (int g = 0; g < 2; g++) {
            int r = wid * 32 + g * 16 + (lane & 15);
            #pragma unroll
            for (int kt = 0; kt < 4; kt++)
                ldsm4(aq[g][kt], s2u(Qs + r * QKV_STRIDE + kt * 16 + ch));
        }
    }

    float of[2][8][4];
    #pragma unroll
    for (int g = 0; g < 2; g++)
        #pragma unroll
        for (int j = 0; j < 8; j++)
            #pragma unroll
            for (int c = 0; c < 4; c++) of[g][j][c] = 0.f;
    float m_[2][2] = {{-1e30f, -1e30f}, {-1e30f, -1e30f}};
    float l_[2][2] = {{0.f, 0.f}, {0.f, 0.f}};
    const float cs_ = 0.125f * LOG2E;
    const uint32_t ones2 = 0x3C003C00u;
    const uint32_t ob[2] = { ones2, ones2 };

    for (int t = 0; t < S_ / 64; t++) {
        CP_WAIT(0);
        __syncthreads();
        if (t + 1 < S_ / 64) load_kv(t + 1, (t + 1) & 1);
        CP_COMMIT();

        const __half* kb = Ks + (t & 1) * KV_SZ;
        const __half* vb = Vs + (t & 1) * KV_SZ;

        // S = Q @ K^T for both groups (K frags loaded once)
        float sf[2][8][4];
        #pragma unroll
        for (int g = 0; g < 2; g++)
            #pragma unroll
            for (int j = 0; j < 8; j++)
                #pragma unroll
                for (int c = 0; c < 4; c++) sf[g][j][c] = 0.f;

        #pragma unroll
        for (int kt = 0; kt < 4; kt++) {
            #pragma unroll
            for (int jp = 0; jp < 4; jp++) {
                uint32_t rr[4];
                ldsm4(rr, s2u(kb + (jp * 16 + (lane & 15)) * QKV_STRIDE +
                              kt * 16 + ((lane >> 4) << 3)));
                uint32_t blo[2] = { rr[0], rr[2] };
                uint32_t bhi[2] = { rr[1], rr[3] };
                mma_f16(sf[0][jp * 2], aq[0][kt], blo);
                mma_f16(sf[0][jp * 2 + 1], aq[0][kt], bhi);
                mma_f16(sf[1][jp * 2], aq[1][kt], blo);
                mma_f16(sf[1][jp * 2 + 1], aq[1][kt], bhi);
            }
        }

        // softmax + P frags per group
        uint32_t pa[2][4][4];
        #pragma unroll
        for (int g = 0; g < 2; g++) {
            float mx0 = -1e30f, mx1 = -1e30f;
            #pragma unroll
            for (int j = 0; j < 8; j++) {
                mx0 = fmaxf(mx0, fmaxf(sf[g][j][0], sf[g][j][1]));
                mx1 = fmaxf(mx1, fmaxf(sf[g][j][2], sf[g][j][3]));
            }
            mx0 = fmaxf(mx0, __shfl_xor_sync(0xffffffffu, mx0, 1, 4));
            mx0 = fmaxf(mx0, __shfl_xor_sync(0xffffffffu, mx0, 2, 4));
            mx1 = fmaxf(mx1, __shfl_xor_sync(0xffffffffu, mx1, 1, 4));
            mx1 = fmaxf(mx1, __shfl_xor_sync(0xffffffffu, mx1, 2, 4));

            if (mx0 > m_[g][0]) {
                float alpha = ex2f((m_[g][0] - mx0) * cs_);
                m_[g][0] = mx0; l_[g][0] *= alpha;
                #pragma unroll
                for (int j = 0; j < 8; j++) { of[g][j][0] *= alpha; of[g][j][1] *= alpha; }
            }
            if (mx1 > m_[g][1]) {
                float alpha = ex2f((m_[g][1] - mx1) * cs_);
                m_[g][1] = mx1; l_[g][1] *= alpha;
                #pragma unroll
                for (int j = 0; j < 8; j++) { of[g][j][2] *= alpha; of[g][j][3] *= alpha; }
            }

            float nm0 = -m_[g][0] * cs_, nm1 = -m_[g][1] * cs_;
            #pragma unroll
            for (int kk = 0; kk < 4; kk++) {
                int ja = 2 * kk, jb = 2 * kk + 1;
                pa[g][kk][0] = h2exp2(pack_h2(fmaf(sf[g][ja][0], cs_, nm0),
                                              fmaf(sf[g][ja][1], cs_, nm0)));
                pa[g][kk][1] = h2exp2(pack_h2(fmaf(sf[g][ja][2], cs_, nm1),
                                              fmaf(sf[g][ja][3], cs_, nm1)));
                pa[g][kk][2] = h2exp2(pack_h2(fmaf(sf[g][jb][0], cs_, nm0),
                                              fmaf(sf[g][jb][1], cs_, nm0)));
                pa[g][kk][3] = h2exp2(pack_h2(fmaf(sf[g][jb][2], cs_, nm1),
                                              fmaf(sf[g][jb][3], cs_, nm1)));
            }

            // row sums l += P @ ones (tensor core, matches fp16 P exactly)
            float lacc[4] = { 0.f, 0.f, 0.f, 0.f };
            #pragma unroll
            for (int kk = 0; kk < 4; kk++)
                mma_f16(lacc, pa[g][kk], ob);
            l_[g][0] += lacc[0];
            l_[g][1] += lacc[2];
        }

        // O += P @ V for both groups (V frags loaded once)
        #pragma unroll
        for (int kk = 0; kk < 4; kk++) {
            #pragma unroll
            for (int jp = 0; jp < 4; jp++) {
                uint32_t rr[4];
                ldsm4t(rr, s2u(vb + (kk * 16 + (lane & 15)) * QKV_STRIDE +
                               jp * 16 + ((lane >> 4) << 3)));
                uint32_t blo[2] = { rr[0], rr[1] };
                uint32_t bhi[2] = { rr[2], rr[3] };
                mma_f16(of[0][jp * 2], pa[0][kk], blo);
                mma_f16(of[0][jp * 2 + 1], pa[0][kk], bhi);
                mma_f16(of[1][jp * 2], pa[1][kk], blo);
                mma_f16(of[1][jp * 2 + 1], pa[1][kk], bhi);
            }
        }
    }

    #pragma unroll
    for (int g = 0; g < 2; g++) {
        float inv0 = 1.f / l_[g][0], inv1 = 1.f / l_[g][1];
        int r = wid * 32 + g * 16 + (lane >> 2);
        int c0 = (lane & 3) * 2;
        #pragma unroll
        for (int j = 0; j < 8; j++) {
            int col = j * 8 + c0;
            *(__half2*)(O + base + (size_t)(q0 + r) * D_ + col) =
                __floats2half2_rn(of[g][j][0] * inv0, of[g][j][1] * inv0);
            *(__half2*)(O + base + (size_t)(q0 + r + 8) * D_ + col) =
                __floats2half2_rn(of[g][j][2] * inv1, of[g][j][3] * inv1);
        }
    }
}

// ---------------------------------------------------------------------------
// Launch
// ---------------------------------------------------------------------------
extern "C" void kernel_launch(void* const* d_in, const int* in_sizes, int n_in,
                              void* d_out, int out_size)
{
    const float* x  = (const float*)d_in[0];
    const float* fr = (const float*)d_in[1];
    const float* wq = (const float*)d_in[2];
    const float* bq = (const float*)d_in[3];
    const float* wk = (const float*)d_in[4];
    const float* bk = (const float*)d_in[5];
    const float* wv = (const float*)d_in[6];
    const float* bv = (const float*)d_in[7];
    const float* wo = (const float*)d_in[8];
    const float* bo = (const float*)d_in[9];
    float* out = (float*)d_out;

    __half *xh, *wqh, *wkh, *wvh, *woh, *qh, *kh, *vh, *oh;
    cudaGetSymbolAddress((void**)&xh,  g_xh);
    cudaGetSymbolAddress((void**)&wqh, g_wqh);
    cudaGetSymbolAddress((void**)&wkh, g_wkh);
    cudaGetSymbolAddress((void**)&wvh, g_wvh);
    cudaGetSymbolAddress((void**)&woh, g_woh);
    cudaGetSymbolAddress((void**)&qh,  g_qh);
    cudaGetSymbolAddress((void**)&kh,  g_kh);
    cudaGetSymbolAddress((void**)&vh,  g_vh);
    cudaGetSymbolAddress((void**)&oh,  g_oh);

    cudaFuncSetAttribute(gemm_qkv,
                         cudaFuncAttributeMaxDynamicSharedMemorySize, GEMM_SMEM);
    cudaFuncSetAttribute(gemm_o,
                         cudaFuncAttributeMaxDynamicSharedMemorySize, GEMM_SMEM);
    cudaFuncSetAttribute(attn_mma,
                         cudaFuncAttributeMaxDynamicSharedMemorySize, ATTN_SMEM);

    const int NTOT = B_ * S_ * D_ + 4 * D_ * D_;   // 8M elements
    conv_all<<<NTOT / 1024, 256>>>(x, wq, wk, wv, wo, xh, wqh, wkh, wvh, woh);

    dim3 gq(D_ / 128, (B_ * S_) / 128, 3);   // (8, 32, 3)
    gemm_qkv<<<gq, 128, GEMM_SMEM>>>(xh, wqh, wkh, wvh, bq, bk, bv, fr, qh, kh, vh);

    attn_mma<<<dim3(S_ / 128, H_, B_), 128, ATTN_SMEM>>>(qh, kh, vh, oh);

    dim3 gg(D_ / 128, (B_ * S_) / 128);      // (8, 32)
    gemm_o<<<gg, 128, GEMM_SMEM>>>(oh, woh, bo, out);
}